// round 8
// baseline (speedup 1.0000x reference)
#include <cuda_runtime.h>
#include <math.h>

#define NN   50000
#define EE   1600000
#define IND  256
#define HD   64
#define CD   16
#define NTR  5000
#define NH   (NN*HD)
#define SCB  ((NN + 255) / 256)   // 196 scan blocks

// Scratch (no allocs allowed)
__device__ __align__(16) float  g_t[NH];       // x @ W
__device__ __align__(16) float  g_h[NH];       // layer output
__device__ __align__(16) float2 g_edge[EE];    // {src_as_float_bits, norm}, CSR order
__device__ float g_dinv[NN];
__device__ int   g_deg[NN];
__device__ int   g_off[NN + 1];
__device__ int   g_cur[NN];
__device__ int   g_bsum[SCB];

// ---------------------------------------------------------------------------
__device__ __forceinline__ unsigned long long fma2(unsigned long long a,
                                                   unsigned long long b,
                                                   unsigned long long c) {
    unsigned long long d;
    asm("fma.rn.f32x2 %0, %1, %2, %3;" : "=l"(d) : "l"(a), "l"(b), "l"(c));
    return d;
}
union U64F2 { unsigned long long u; float2 f; };
__device__ __forceinline__ float2 asf2(unsigned long long u) {
    U64F2 t; t.u = u; return t.f;
}

// ---------------------------------------------------------------------------
__global__ void k_zero_i(int* p, int n) {
    int i = blockIdx.x * blockDim.x + threadIdx.x;
    if (i < n) p[i] = 0;
}
__global__ void k_deg(const int* __restrict__ dst) {
    int e = blockIdx.x * blockDim.x + threadIdx.x;
    if (e < EE) atomicAdd(&g_deg[dst[e]], 1);
}

// Phase A: per-block exclusive scan (+ fused dinv compute)
__global__ void k_scanA() {
    __shared__ int ss[256];
    int t = threadIdx.x;
    int idx = blockIdx.x * 256 + t;
    int d = (idx < NN) ? g_deg[idx] : 0;
    if (idx < NN) g_dinv[idx] = rsqrtf((float)d + 1.0f);  // +1 self-loop
    ss[t] = d;
    __syncthreads();
#pragma unroll
    for (int o = 1; o < 256; o <<= 1) {
        int v = (t >= o) ? ss[t - o] : 0;
        __syncthreads();
        ss[t] += v;
        __syncthreads();
    }
    int inc = ss[t];
    if (idx < NN) g_off[idx] = inc - d;
    if (t == 255) g_bsum[blockIdx.x] = inc;
}
__global__ void k_scanB() {
    __shared__ int ss[SCB];
    int t = threadIdx.x;
    int v = (t < SCB) ? g_bsum[t] : 0;
    if (t < SCB) ss[t] = v;
    __syncthreads();
    for (int o = 1; o < SCB; o <<= 1) {
        int u = (t >= o && t < SCB) ? ss[t - o] : 0;
        __syncthreads();
        if (t < SCB) ss[t] += u;
        __syncthreads();
    }
    if (t < SCB) g_bsum[t] = ss[t] - v;
}
__global__ void k_scanC() {
    int idx = blockIdx.x * 256 + threadIdx.x;
    if (idx < NN) {
        int o = g_off[idx] + g_bsum[blockIdx.x];
        g_off[idx] = o;
        g_cur[idx] = o;
    }
    if (idx == 0) g_off[NN] = EE;
}

// Bucket edges by dst; one 8B packed store per edge.
__global__ void k_fill(const int* __restrict__ src, const int* __restrict__ dst) {
    int e = blockIdx.x * blockDim.x + threadIdx.x;
    if (e >= EE) return;
    int s = src[e], d = dst[e];
    int pos = atomicAdd(&g_cur[d], 1);
    g_edge[pos] = make_float2(__int_as_float(s), g_dinv[s] * g_dinv[d]);
}

// ---------------------------------------------------------------------------
// O[N,64] = A[N,K] @ W[K,64].  64x64 tile, 128 threads, f32x2 FMA.
// Thread (rg=tid&7, cg=tid>>3): rows rg*8..+7 (as 4 row-pairs), cols cg*4..+3.
template <int K>
__global__ void __launch_bounds__(128) k_gemm(const float* __restrict__ A,
                                              const float* __restrict__ W,
                                              float* __restrict__ O) {
    __shared__ float sAT[64][64];     // [k][row] transposed (row pairs natural)
    __shared__ float sWd[64][128];    // [k][2*col] duplicated (w,w) pairs
    const int tid = threadIdx.x;
    const int rg = tid & 7;
    const int cg = tid >> 3;
    const int rb = blockIdx.x * 64;

    unsigned long long acc[4][4];
#pragma unroll
    for (int i = 0; i < 4; i++)
#pragma unroll
        for (int j = 0; j < 4; j++) acc[i][j] = 0ull;

    for (int kc = 0; kc < K; kc += 64) {
        // stage A transposed: conflict-free STS (lanes -> consecutive rows)
#pragma unroll
        for (int it = 0; it < 8; it++) {
            int i = tid + it * 128;
            int r = i & 63, k4 = i >> 6;
            int row = rb + r;
            float4 v = (row < NN)
                ? *(const float4*)(A + (size_t)row * K + kc + k4 * 4)
                : make_float4(0.f, 0.f, 0.f, 0.f);
            sAT[k4 * 4 + 0][r] = v.x;
            sAT[k4 * 4 + 1][r] = v.y;
            sAT[k4 * 4 + 2][r] = v.z;
            sAT[k4 * 4 + 3][r] = v.w;
        }
        // stage W duplicated
#pragma unroll
        for (int it = 0; it < 8; it++) {
            int i = tid + it * 128;
            int c4 = i & 15, k = i >> 4;
            float4 v = *(const float4*)(W + (size_t)(kc + k) * HD + c4 * 4);
            float2* wp = (float2*)&sWd[k][c4 * 8];
            wp[0] = make_float2(v.x, v.x);
            wp[1] = make_float2(v.y, v.y);
            wp[2] = make_float2(v.z, v.z);
            wp[3] = make_float2(v.w, v.w);
        }
        __syncthreads();
#pragma unroll 8
        for (int k = 0; k < 64; k++) {
            ulonglong2 a01 = *(const ulonglong2*)&sAT[k][rg * 8];
            ulonglong2 a23 = *(const ulonglong2*)&sAT[k][rg * 8 + 4];
            ulonglong2 w01 = *(const ulonglong2*)&sWd[k][cg * 8];
            ulonglong2 w23 = *(const ulonglong2*)&sWd[k][cg * 8 + 4];
            acc[0][0] = fma2(a01.x, w01.x, acc[0][0]);
            acc[0][1] = fma2(a01.x, w01.y, acc[0][1]);
            acc[0][2] = fma2(a01.x, w23.x, acc[0][2]);
            acc[0][3] = fma2(a01.x, w23.y, acc[0][3]);
            acc[1][0] = fma2(a01.y, w01.x, acc[1][0]);
            acc[1][1] = fma2(a01.y, w01.y, acc[1][1]);
            acc[1][2] = fma2(a01.y, w23.x, acc[1][2]);
            acc[1][3] = fma2(a01.y, w23.y, acc[1][3]);
            acc[2][0] = fma2(a23.x, w01.x, acc[2][0]);
            acc[2][1] = fma2(a23.x, w01.y, acc[2][1]);
            acc[2][2] = fma2(a23.x, w23.x, acc[2][2]);
            acc[2][3] = fma2(a23.x, w23.y, acc[2][3]);
            acc[3][0] = fma2(a23.y, w01.x, acc[3][0]);
            acc[3][1] = fma2(a23.y, w01.y, acc[3][1]);
            acc[3][2] = fma2(a23.y, w23.x, acc[3][2]);
            acc[3][3] = fma2(a23.y, w23.y, acc[3][3]);
        }
        __syncthreads();
    }
#pragma unroll
    for (int rp = 0; rp < 4; rp++) {
        float2 c0 = asf2(acc[rp][0]);
        float2 c1 = asf2(acc[rp][1]);
        float2 c2 = asf2(acc[rp][2]);
        float2 c3 = asf2(acc[rp][3]);
        int row0 = rb + rg * 8 + rp * 2;
        if (row0 < NN)
            *(float4*)(O + (size_t)row0 * HD + cg * 4) =
                make_float4(c0.x, c1.x, c2.x, c3.x);
        if (row0 + 1 < NN)
            *(float4*)(O + (size_t)(row0 + 1) * HD + cg * 4) =
                make_float4(c0.y, c1.y, c2.y, c3.y);
    }
}

// ---------------------------------------------------------------------------
// CSR gather: 16 threads/node (one float4 lane each), 2-way unrolled,
// self-loop + bias + relu fused.
__global__ void __launch_bounds__(256) k_gather(const float* __restrict__ t,
                                                float* __restrict__ h,
                                                const float* __restrict__ b,
                                                int relu) {
    int node = blockIdx.x * 16 + (threadIdx.x >> 4);
    int q = threadIdx.x & 15;
    if (node >= NN) return;
    const float4* tv = (const float4*)t;

    float di = g_dinv[node];
    float4 sv = tv[(size_t)node * 16 + q];
    float di2 = di * di;
    float4 acc = make_float4(sv.x * di2, sv.y * di2, sv.z * di2, sv.w * di2);
    float4 acc2 = make_float4(0.f, 0.f, 0.f, 0.f);

    int beg = g_off[node], end = g_off[node + 1];
    int i = beg;
    for (; i + 2 <= end; i += 2) {
        float2 e0 = g_edge[i];
        float2 e1 = g_edge[i + 1];
        int s0 = __float_as_int(e0.x);
        int s1 = __float_as_int(e1.x);
        float4 v0 = tv[(size_t)s0 * 16 + q];
        float4 v1 = tv[(size_t)s1 * 16 + q];
        acc.x += e0.y * v0.x;  acc.y += e0.y * v0.y;
        acc.z += e0.y * v0.z;  acc.w += e0.y * v0.w;
        acc2.x += e1.y * v1.x; acc2.y += e1.y * v1.y;
        acc2.z += e1.y * v1.z; acc2.w += e1.y * v1.w;
    }
    if (i < end) {
        float2 e0 = g_edge[i];
        int s0 = __float_as_int(e0.x);
        float4 v0 = tv[(size_t)s0 * 16 + q];
        acc.x += e0.y * v0.x; acc.y += e0.y * v0.y;
        acc.z += e0.y * v0.z; acc.w += e0.y * v0.w;
    }
    acc.x += acc2.x; acc.y += acc2.y; acc.z += acc2.z; acc.w += acc2.w;

    float4 bb = ((const float4*)b)[q];
    acc.x += bb.x; acc.y += bb.y; acc.z += bb.z; acc.w += bb.w;
    if (relu) {
        acc.x = fmaxf(acc.x, 0.f);
        acc.y = fmaxf(acc.y, 0.f);
        acc.z = fmaxf(acc.z, 0.f);
        acc.w = fmaxf(acc.w, 0.f);
    }
    ((float4*)h)[(size_t)node * 16 + q] = acc;
}

// ---------------------------------------------------------------------------
// Fused: L2-normalize row -> out_h (scalar stores; view only 4B-aligned),
// then logits @ W3 + b3 -> log_softmax -> out_pred.
__global__ void k_normpred(const float* __restrict__ h, float* __restrict__ out_h,
                           const float* __restrict__ W3, const float* __restrict__ b3,
                           float* __restrict__ pred) {
    __shared__ float sW[HD * CD];
    __shared__ float sb[CD];
    for (int i = threadIdx.x; i < HD * CD; i += blockDim.x) sW[i] = W3[i];
    if (threadIdx.x < CD) sb[threadIdx.x] = b3[threadIdx.x];
    __syncthreads();
    int n = blockIdx.x * blockDim.x + threadIdx.x;
    if (n >= NN) return;

    const float4* hv = (const float4*)(h + (size_t)n * HD);
    float4 r[16];
    float ss = 0.f;
#pragma unroll
    for (int i = 0; i < 16; i++) {
        float4 v = hv[i];
        r[i] = v;
        ss += v.x * v.x + v.y * v.y + v.z * v.z + v.w * v.w;
    }
    float sc = 1.0f / fmaxf(sqrtf(ss), 1e-12f);

    float z[CD];
#pragma unroll
    for (int c = 0; c < CD; c++) z[c] = sb[c];
    float* oo = out_h + (size_t)n * HD;
#pragma unroll
    for (int k4 = 0; k4 < 16; k4++) {
        float4 v = r[k4];
        v.x *= sc; v.y *= sc; v.z *= sc; v.w *= sc;
        oo[k4 * 4 + 0] = v.x;
        oo[k4 * 4 + 1] = v.y;
        oo[k4 * 4 + 2] = v.z;
        oo[k4 * 4 + 3] = v.w;
        const float* w0 = &sW[(k4 * 4 + 0) * CD];
        const float* w1 = &sW[(k4 * 4 + 1) * CD];
        const float* w2 = &sW[(k4 * 4 + 2) * CD];
        const float* w3 = &sW[(k4 * 4 + 3) * CD];
#pragma unroll
        for (int c = 0; c < CD; c++)
            z[c] += v.x * w0[c] + v.y * w1[c] + v.z * w2[c] + v.w * w3[c];
    }
    float m = z[0];
#pragma unroll
    for (int c = 1; c < CD; c++) m = fmaxf(m, z[c]);
    float se = 0.f;
#pragma unroll
    for (int c = 0; c < CD; c++) se += expf(z[c] - m);
    float lse = m + logf(se);
    float* po = pred + (size_t)n * CD;
#pragma unroll
    for (int c = 0; c < CD; c++) po[c] = z[c] - lse;
}

// NLL loss over train indices — single block, deterministic reduce
__global__ void k_loss(const float* __restrict__ pred, const int* __restrict__ labels,
                       const int* __restrict__ tidx, float* __restrict__ out) {
    __shared__ float sred[256];
    float s = 0.f;
    for (int i = threadIdx.x; i < NTR; i += 256) {
        int idx = tidx[i];
        s += pred[(size_t)idx * CD + labels[idx]];
    }
    sred[threadIdx.x] = s;
    __syncthreads();
    for (int o = 128; o > 0; o >>= 1) {
        if (threadIdx.x < o) sred[threadIdx.x] += sred[threadIdx.x + o];
        __syncthreads();
    }
    if (threadIdx.x == 0) out[0] = -sred[0] / (float)NTR;
}

// ---------------------------------------------------------------------------
extern "C" void kernel_launch(void* const* d_in, const int* in_sizes, int n_in,
                              void* d_out, int out_size) {
    const float* feats  = (const float*)d_in[0];
    const float* W1     = (const float*)d_in[1];
    const float* b1     = (const float*)d_in[2];
    const float* W2     = (const float*)d_in[3];
    const float* b2     = (const float*)d_in[4];
    const float* W3     = (const float*)d_in[5];
    const float* b3     = (const float*)d_in[6];
    const int*   edges  = (const int*)d_in[7];
    const int*   labels = (const int*)d_in[8];
    const int*   tidx   = (const int*)d_in[9];

    float* out      = (float*)d_out;
    float* out_pred = out + 1;
    float* out_h    = out + 1 + (size_t)NN * CD;

    float* t_ptr;  cudaGetSymbolAddress((void**)&t_ptr, g_t);
    float* h_ptr;  cudaGetSymbolAddress((void**)&h_ptr, g_h);
    int*   deg_ptr; cudaGetSymbolAddress((void**)&deg_ptr, g_deg);

    const int* src = edges;        // edge_list[0]
    const int* dst = edges + EE;   // edge_list[1]

    // ---- CSR build
    k_zero_i<<<(NN + 255) / 256, 256>>>(deg_ptr, NN);
    k_deg<<<(EE + 255) / 256, 256>>>(dst);
    k_scanA<<<SCB, 256>>>();
    k_scanB<<<1, 256>>>();
    k_scanC<<<SCB, 256>>>();
    k_fill<<<(EE + 255) / 256, 256>>>(src, dst);

    const int gemm_blocks = (NN + 63) / 64;
    const int gath_blocks = (NN + 15) / 16;

    // Layer 0: feats -> h0  (no relu)
    k_gemm<IND><<<gemm_blocks, 128>>>(feats, W1, t_ptr);
    k_gather<<<gath_blocks, 256>>>(t_ptr, h_ptr, b1, 0);

    // Hidden layers (relu)
    for (int l = 0; l < 2; l++) {
        k_gemm<HD><<<gemm_blocks, 128>>>(h_ptr, W2 + (size_t)l * HD * HD, t_ptr);
        k_gather<<<gath_blocks, 256>>>(t_ptr, h_ptr, b2 + (size_t)l * HD, 1);
    }

    // normalize + out_h + logits + log_softmax ; then nll
    k_normpred<<<(NN + 255) / 256, 256>>>(h_ptr, out_h, W3, b3, out_pred);
    k_loss<<<1, 256>>>(out_pred, labels, tidx, out);
}

// round 9
// speedup vs baseline: 1.0517x; 1.0517x over previous
#include <cuda_runtime.h>
#include <math.h>

#define NN   50000
#define EE   1600000
#define IND  256
#define HD   64
#define CD   16
#define NTR  5000
#define NH   (NN*HD)
#define SCB  ((NN + 255) / 256)   // 196 scan blocks

// Scratch (no allocs allowed)
__device__ __align__(16) float  g_t[NH];       // x @ W
__device__ __align__(16) float  g_h[NH];       // layer output
__device__ __align__(16) float2 g_edge[EE];    // {src_as_float_bits, norm}, CSR order
__device__ float g_dinv[NN];
__device__ int   g_deg[NN];
__device__ int   g_off[NN + 1];
__device__ int   g_cur[NN];
__device__ int   g_bsum[SCB];

// ---------------------------------------------------------------------------
__device__ __forceinline__ unsigned long long fma2(unsigned long long a,
                                                   unsigned long long b,
                                                   unsigned long long c) {
    unsigned long long d;
    asm("fma.rn.f32x2 %0, %1, %2, %3;" : "=l"(d) : "l"(a), "l"(b), "l"(c));
    return d;
}
union U64F2 { unsigned long long u; float2 f; };
__device__ __forceinline__ float2 asf2(unsigned long long u) {
    U64F2 t; t.u = u; return t.f;
}

// ---------------------------------------------------------------------------
__global__ void k_zero_i(int* p, int n) {
    int i = blockIdx.x * blockDim.x + threadIdx.x;
    if (i < n) p[i] = 0;
}
__global__ void k_deg(const int* __restrict__ dst) {
    int e = blockIdx.x * blockDim.x + threadIdx.x;
    if (e < EE) atomicAdd(&g_deg[dst[e]], 1);
}

// Phase A: per-block exclusive scan (+ fused dinv compute)
__global__ void k_scanA() {
    __shared__ int ss[256];
    int t = threadIdx.x;
    int idx = blockIdx.x * 256 + t;
    int d = (idx < NN) ? g_deg[idx] : 0;
    if (idx < NN) g_dinv[idx] = rsqrtf((float)d + 1.0f);  // +1 self-loop
    ss[t] = d;
    __syncthreads();
#pragma unroll
    for (int o = 1; o < 256; o <<= 1) {
        int v = (t >= o) ? ss[t - o] : 0;
        __syncthreads();
        ss[t] += v;
        __syncthreads();
    }
    int inc = ss[t];
    if (idx < NN) g_off[idx] = inc - d;
    if (t == 255) g_bsum[blockIdx.x] = inc;
}
__global__ void k_scanB() {
    __shared__ int ss[SCB];
    int t = threadIdx.x;
    int v = (t < SCB) ? g_bsum[t] : 0;
    if (t < SCB) ss[t] = v;
    __syncthreads();
    for (int o = 1; o < SCB; o <<= 1) {
        int u = (t >= o && t < SCB) ? ss[t - o] : 0;
        __syncthreads();
        if (t < SCB) ss[t] += u;
        __syncthreads();
    }
    if (t < SCB) g_bsum[t] = ss[t] - v;
}
__global__ void k_scanC() {
    int idx = blockIdx.x * 256 + threadIdx.x;
    if (idx < NN) {
        int o = g_off[idx] + g_bsum[blockIdx.x];
        g_off[idx] = o;
        g_cur[idx] = o;
    }
    if (idx == 0) g_off[NN] = EE;
}

// Bucket edges by dst; one 8B packed store per edge.
__global__ void k_fill(const int* __restrict__ src, const int* __restrict__ dst) {
    int e = blockIdx.x * blockDim.x + threadIdx.x;
    if (e >= EE) return;
    int s = src[e], d = dst[e];
    int pos = atomicAdd(&g_cur[d], 1);
    g_edge[pos] = make_float2(__int_as_float(s), g_dinv[s] * g_dinv[d]);
}

// ---------------------------------------------------------------------------
// O[N,64] = A[N,K] @ W[K,64].  128x64 tile, 256 threads, K-chunk 32, f32x2 FMA.
// Thread (rg=tid&15, cg=tid>>4): rows rg*8..+7 (4 row-pairs), cols cg*4..+3.
template <int K>
__global__ void __launch_bounds__(256) k_gemm(const float* __restrict__ A,
                                              const float* __restrict__ W,
                                              float* __restrict__ O) {
    __shared__ __align__(16) float sAT[32][132];   // [k][row], padded
    __shared__ __align__(16) float sWd[32][136];   // [k][2*col] dup pairs, padded
    const int tid = threadIdx.x;
    const int rg = tid & 15;
    const int cg = tid >> 4;
    const int rb = blockIdx.x * 128;

    unsigned long long acc[4][4];
#pragma unroll
    for (int i = 0; i < 4; i++)
#pragma unroll
        for (int j = 0; j < 4; j++) acc[i][j] = 0ull;

    for (int kc = 0; kc < K; kc += 32) {
        // stage A transposed: 128 rows x 32 k = 1024 float4
#pragma unroll
        for (int it = 0; it < 4; it++) {
            int i = tid + it * 256;
            int r = i >> 3, k4 = i & 7;
            int row = rb + r;
            float4 v = (row < NN)
                ? *(const float4*)(A + (size_t)row * K + kc + k4 * 4)
                : make_float4(0.f, 0.f, 0.f, 0.f);
            sAT[k4 * 4 + 0][r] = v.x;
            sAT[k4 * 4 + 1][r] = v.y;
            sAT[k4 * 4 + 2][r] = v.z;
            sAT[k4 * 4 + 3][r] = v.w;
        }
        // stage W duplicated: 32 k x 64 cols = 512 float4
#pragma unroll
        for (int it = 0; it < 2; it++) {
            int i = tid + it * 256;
            int c4 = i & 15, k = i >> 4;
            float4 v = *(const float4*)(W + (size_t)(kc + k) * HD + c4 * 4);
            float2* wp = (float2*)&sWd[k][c4 * 8];
            wp[0] = make_float2(v.x, v.x);
            wp[1] = make_float2(v.y, v.y);
            wp[2] = make_float2(v.z, v.z);
            wp[3] = make_float2(v.w, v.w);
        }
        __syncthreads();
#pragma unroll 8
        for (int k = 0; k < 32; k++) {
            ulonglong2 a01 = *(const ulonglong2*)&sAT[k][rg * 8];
            ulonglong2 a23 = *(const ulonglong2*)&sAT[k][rg * 8 + 4];
            ulonglong2 w01 = *(const ulonglong2*)&sWd[k][cg * 8];
            ulonglong2 w23 = *(const ulonglong2*)&sWd[k][cg * 8 + 4];
            acc[0][0] = fma2(a01.x, w01.x, acc[0][0]);
            acc[0][1] = fma2(a01.x, w01.y, acc[0][1]);
            acc[0][2] = fma2(a01.x, w23.x, acc[0][2]);
            acc[0][3] = fma2(a01.x, w23.y, acc[0][3]);
            acc[1][0] = fma2(a01.y, w01.x, acc[1][0]);
            acc[1][1] = fma2(a01.y, w01.y, acc[1][1]);
            acc[1][2] = fma2(a01.y, w23.x, acc[1][2]);
            acc[1][3] = fma2(a01.y, w23.y, acc[1][3]);
            acc[2][0] = fma2(a23.x, w01.x, acc[2][0]);
            acc[2][1] = fma2(a23.x, w01.y, acc[2][1]);
            acc[2][2] = fma2(a23.x, w23.x, acc[2][2]);
            acc[2][3] = fma2(a23.x, w23.y, acc[2][3]);
            acc[3][0] = fma2(a23.y, w01.x, acc[3][0]);
            acc[3][1] = fma2(a23.y, w01.y, acc[3][1]);
            acc[3][2] = fma2(a23.y, w23.x, acc[3][2]);
            acc[3][3] = fma2(a23.y, w23.y, acc[3][3]);
        }
        __syncthreads();
    }
#pragma unroll
    for (int rp = 0; rp < 4; rp++) {
        float2 c0 = asf2(acc[rp][0]);
        float2 c1 = asf2(acc[rp][1]);
        float2 c2 = asf2(acc[rp][2]);
        float2 c3 = asf2(acc[rp][3]);
        int row0 = rb + rg * 8 + rp * 2;
        if (row0 < NN)
            *(float4*)(O + (size_t)row0 * HD + cg * 4) =
                make_float4(c0.x, c1.x, c2.x, c3.x);
        if (row0 + 1 < NN)
            *(float4*)(O + (size_t)(row0 + 1) * HD + cg * 4) =
                make_float4(c0.y, c1.y, c2.y, c3.y);
    }
}

// ---------------------------------------------------------------------------
// CSR gather: 16 threads/node (one float4 lane each), 2-way unrolled,
// self-loop + bias + relu fused.
__global__ void __launch_bounds__(256) k_gather(const float* __restrict__ t,
                                                float* __restrict__ h,
                                                const float* __restrict__ b,
                                                int relu) {
    int node = blockIdx.x * 16 + (threadIdx.x >> 4);
    int q = threadIdx.x & 15;
    if (node >= NN) return;
    const float4* tv = (const float4*)t;

    float di = g_dinv[node];
    float4 sv = tv[(size_t)node * 16 + q];
    float di2 = di * di;
    float4 acc = make_float4(sv.x * di2, sv.y * di2, sv.z * di2, sv.w * di2);
    float4 acc2 = make_float4(0.f, 0.f, 0.f, 0.f);

    int beg = g_off[node], end = g_off[node + 1];
    int i = beg;
    for (; i + 2 <= end; i += 2) {
        float2 e0 = __ldg(&g_edge[i]);
        float2 e1 = __ldg(&g_edge[i + 1]);
        int s0 = __float_as_int(e0.x);
        int s1 = __float_as_int(e1.x);
        float4 v0 = tv[(size_t)s0 * 16 + q];
        float4 v1 = tv[(size_t)s1 * 16 + q];
        acc.x += e0.y * v0.x;  acc.y += e0.y * v0.y;
        acc.z += e0.y * v0.z;  acc.w += e0.y * v0.w;
        acc2.x += e1.y * v1.x; acc2.y += e1.y * v1.y;
        acc2.z += e1.y * v1.z; acc2.w += e1.y * v1.w;
    }
    if (i < end) {
        float2 e0 = __ldg(&g_edge[i]);
        int s0 = __float_as_int(e0.x);
        float4 v0 = tv[(size_t)s0 * 16 + q];
        acc.x += e0.y * v0.x; acc.y += e0.y * v0.y;
        acc.z += e0.y * v0.z; acc.w += e0.y * v0.w;
    }
    acc.x += acc2.x; acc.y += acc2.y; acc.z += acc2.z; acc.w += acc2.w;

    float4 bb = ((const float4*)b)[q];
    acc.x += bb.x; acc.y += bb.y; acc.z += bb.z; acc.w += bb.w;
    if (relu) {
        acc.x = fmaxf(acc.x, 0.f);
        acc.y = fmaxf(acc.y, 0.f);
        acc.z = fmaxf(acc.z, 0.f);
        acc.w = fmaxf(acc.w, 0.f);
    }
    ((float4*)h)[(size_t)node * 16 + q] = acc;
}

// ---------------------------------------------------------------------------
// Fused: L2-normalize row -> out_h (scalar stores; view only 4B-aligned),
// then logits @ W3 + b3 -> log_softmax -> out_pred.
__global__ void k_normpred(const float* __restrict__ h, float* __restrict__ out_h,
                           const float* __restrict__ W3, const float* __restrict__ b3,
                           float* __restrict__ pred) {
    __shared__ float sW[HD * CD];
    __shared__ float sb[CD];
    for (int i = threadIdx.x; i < HD * CD; i += blockDim.x) sW[i] = W3[i];
    if (threadIdx.x < CD) sb[threadIdx.x] = b3[threadIdx.x];
    __syncthreads();
    int n = blockIdx.x * blockDim.x + threadIdx.x;
    if (n >= NN) return;

    const float4* hv = (const float4*)(h + (size_t)n * HD);
    float4 r[16];
    float ss = 0.f;
#pragma unroll
    for (int i = 0; i < 16; i++) {
        float4 v = hv[i];
        r[i] = v;
        ss += v.x * v.x + v.y * v.y + v.z * v.z + v.w * v.w;
    }
    float sc = 1.0f / fmaxf(sqrtf(ss), 1e-12f);

    float z[CD];
#pragma unroll
    for (int c = 0; c < CD; c++) z[c] = sb[c];
    float* oo = out_h + (size_t)n * HD;
#pragma unroll
    for (int k4 = 0; k4 < 16; k4++) {
        float4 v = r[k4];
        v.x *= sc; v.y *= sc; v.z *= sc; v.w *= sc;
        oo[k4 * 4 + 0] = v.x;
        oo[k4 * 4 + 1] = v.y;
        oo[k4 * 4 + 2] = v.z;
        oo[k4 * 4 + 3] = v.w;
        const float* w0 = &sW[(k4 * 4 + 0) * CD];
        const float* w1 = &sW[(k4 * 4 + 1) * CD];
        const float* w2 = &sW[(k4 * 4 + 2) * CD];
        const float* w3 = &sW[(k4 * 4 + 3) * CD];
#pragma unroll
        for (int c = 0; c < CD; c++)
            z[c] += v.x * w0[c] + v.y * w1[c] + v.z * w2[c] + v.w * w3[c];
    }
    float m = z[0];
#pragma unroll
    for (int c = 1; c < CD; c++) m = fmaxf(m, z[c]);
    float se = 0.f;
#pragma unroll
    for (int c = 0; c < CD; c++) se += expf(z[c] - m);
    float lse = m + logf(se);
    float* po = pred + (size_t)n * CD;
#pragma unroll
    for (int c = 0; c < CD; c++) po[c] = z[c] - lse;
}

// NLL loss over train indices — single block, deterministic reduce
__global__ void k_loss(const float* __restrict__ pred, const int* __restrict__ labels,
                       const int* __restrict__ tidx, float* __restrict__ out) {
    __shared__ float sred[256];
    float s = 0.f;
    for (int i = threadIdx.x; i < NTR; i += 256) {
        int idx = tidx[i];
        s += pred[(size_t)idx * CD + labels[idx]];
    }
    sred[threadIdx.x] = s;
    __syncthreads();
    for (int o = 128; o > 0; o >>= 1) {
        if (threadIdx.x < o) sred[threadIdx.x] += sred[threadIdx.x + o];
        __syncthreads();
    }
    if (threadIdx.x == 0) out[0] = -sred[0] / (float)NTR;
}

// ---------------------------------------------------------------------------
extern "C" void kernel_launch(void* const* d_in, const int* in_sizes, int n_in,
                              void* d_out, int out_size) {
    const float* feats  = (const float*)d_in[0];
    const float* W1     = (const float*)d_in[1];
    const float* b1     = (const float*)d_in[2];
    const float* W2     = (const float*)d_in[3];
    const float* b2     = (const float*)d_in[4];
    const float* W3     = (const float*)d_in[5];
    const float* b3     = (const float*)d_in[6];
    const int*   edges  = (const int*)d_in[7];
    const int*   labels = (const int*)d_in[8];
    const int*   tidx   = (const int*)d_in[9];

    float* out      = (float*)d_out;
    float* out_pred = out + 1;
    float* out_h    = out + 1 + (size_t)NN * CD;

    float* t_ptr;  cudaGetSymbolAddress((void**)&t_ptr, g_t);
    float* h_ptr;  cudaGetSymbolAddress((void**)&h_ptr, g_h);
    int*   deg_ptr; cudaGetSymbolAddress((void**)&deg_ptr, g_deg);

    const int* src = edges;        // edge_list[0]
    const int* dst = edges + EE;   // edge_list[1]

    const int gemm_blocks = (NN + 127) / 128;
    const int gath_blocks = (NN + 15) / 16;

    // Layer-0 GEMM first (independent of CSR build)
    k_gemm<IND><<<gemm_blocks, 256>>>(feats, W1, t_ptr);

    // ---- CSR build
    k_zero_i<<<(NN + 255) / 256, 256>>>(deg_ptr, NN);
    k_deg<<<(EE + 255) / 256, 256>>>(dst);
    k_scanA<<<SCB, 256>>>();
    k_scanB<<<1, 256>>>();
    k_scanC<<<SCB, 256>>>();
    k_fill<<<(EE + 255) / 256, 256>>>(src, dst);

    // Layer 0 aggregate (no relu)
    k_gather<<<gath_blocks, 256>>>(t_ptr, h_ptr, b1, 0);

    // Hidden layers (relu)
    for (int l = 0; l < 2; l++) {
        k_gemm<HD><<<gemm_blocks, 256>>>(h_ptr, W2 + (size_t)l * HD * HD, t_ptr);
        k_gather<<<gath_blocks, 256>>>(t_ptr, h_ptr, b2 + (size_t)l * HD, 1);
    }

    // normalize + out_h + logits + log_softmax ; then nll
    k_normpred<<<(NN + 255) / 256, 256>>>(h_ptr, out_h, W3, b3, out_pred);
    k_loss<<<1, 256>>>(out_pred, labels, tidx, out);
}

// round 10
// speedup vs baseline: 1.0828x; 1.0295x over previous
#include <cuda_runtime.h>
#include <math.h>

#define NN   50000
#define EE   1600000
#define IND  256
#define HD   64
#define CD   16
#define NTR  5000
#define NH   (NN*HD)
#define SCB  ((NN + 255) / 256)   // 196 scan blocks

// Scratch (no allocs allowed)
__device__ __align__(16) float  g_t[NH];       // x @ W
__device__ __align__(16) float  g_h[NH];       // layer output
__device__ __align__(16) float2 g_edge[EE];    // {src_as_float_bits, norm}, CSR order
__device__ float g_dinv[NN];
__device__ int   g_deg[NN];
__device__ int   g_off[NN + 1];
__device__ int   g_cur[NN];
__device__ int   g_bsum[SCB];

// ---------------------------------------------------------------------------
__device__ __forceinline__ unsigned long long fma2(unsigned long long a,
                                                   unsigned long long b,
                                                   unsigned long long c) {
    unsigned long long d;
    asm("fma.rn.f32x2 %0, %1, %2, %3;" : "=l"(d) : "l"(a), "l"(b), "l"(c));
    return d;
}
union U64F2 { unsigned long long u; float2 f; };
__device__ __forceinline__ float2 asf2(unsigned long long u) {
    U64F2 t; t.u = u; return t.f;
}

// ---------------------------------------------------------------------------
__global__ void k_zero_i(int* p, int n) {
    int i = blockIdx.x * blockDim.x + threadIdx.x;
    if (i < n) p[i] = 0;
}
__global__ void k_deg(const int* __restrict__ dst) {
    int e = blockIdx.x * blockDim.x + threadIdx.x;
    if (e < EE) atomicAdd(&g_deg[dst[e]], 1);
}

// Phase A: per-block exclusive scan (+ fused dinv compute)
__global__ void k_scanA() {
    __shared__ int ss[256];
    int t = threadIdx.x;
    int idx = blockIdx.x * 256 + t;
    int d = (idx < NN) ? g_deg[idx] : 0;
    if (idx < NN) g_dinv[idx] = rsqrtf((float)d + 1.0f);  // +1 self-loop
    ss[t] = d;
    __syncthreads();
#pragma unroll
    for (int o = 1; o < 256; o <<= 1) {
        int v = (t >= o) ? ss[t - o] : 0;
        __syncthreads();
        ss[t] += v;
        __syncthreads();
    }
    int inc = ss[t];
    if (idx < NN) g_off[idx] = inc - d;
    if (t == 255) g_bsum[blockIdx.x] = inc;
}
__global__ void k_scanB() {
    __shared__ int ss[SCB];
    int t = threadIdx.x;
    int v = (t < SCB) ? g_bsum[t] : 0;
    if (t < SCB) ss[t] = v;
    __syncthreads();
    for (int o = 1; o < SCB; o <<= 1) {
        int u = (t >= o && t < SCB) ? ss[t - o] : 0;
        __syncthreads();
        if (t < SCB) ss[t] += u;
        __syncthreads();
    }
    if (t < SCB) g_bsum[t] = ss[t] - v;
}
__global__ void k_scanC() {
    int idx = blockIdx.x * 256 + threadIdx.x;
    if (idx < NN) {
        int o = g_off[idx] + g_bsum[blockIdx.x];
        g_off[idx] = o;
        g_cur[idx] = o;
    }
    if (idx == 0) g_off[NN] = EE;
}

// Bucket edges by dst; one 8B packed store per edge.
__global__ void k_fill(const int* __restrict__ src, const int* __restrict__ dst) {
    int e = blockIdx.x * blockDim.x + threadIdx.x;
    if (e >= EE) return;
    int s = src[e], d = dst[e];
    int pos = atomicAdd(&g_cur[d], 1);
    g_edge[pos] = make_float2(__int_as_float(s), g_dinv[s] * g_dinv[d]);
}

// ---------------------------------------------------------------------------
// O[N,64] = A[N,K] @ W[K,64].  128x64 tile, 256 threads, K-chunk 32, f32x2 FMA.
template <int K>
__global__ void __launch_bounds__(256) k_gemm(const float* __restrict__ A,
                                              const float* __restrict__ W,
                                              float* __restrict__ O) {
    __shared__ __align__(16) float sAT[32][132];   // [k][row], padded
    __shared__ __align__(16) float sWd[32][136];   // [k][2*col] dup pairs, padded
    const int tid = threadIdx.x;
    const int rg = tid & 15;
    const int cg = tid >> 4;
    const int rb = blockIdx.x * 128;

    unsigned long long acc[4][4];
#pragma unroll
    for (int i = 0; i < 4; i++)
#pragma unroll
        for (int j = 0; j < 4; j++) acc[i][j] = 0ull;

    for (int kc = 0; kc < K; kc += 32) {
#pragma unroll
        for (int it = 0; it < 4; it++) {
            int i = tid + it * 256;
            int r = i >> 3, k4 = i & 7;
            int row = rb + r;
            float4 v = (row < NN)
                ? *(const float4*)(A + (size_t)row * K + kc + k4 * 4)
                : make_float4(0.f, 0.f, 0.f, 0.f);
            sAT[k4 * 4 + 0][r] = v.x;
            sAT[k4 * 4 + 1][r] = v.y;
            sAT[k4 * 4 + 2][r] = v.z;
            sAT[k4 * 4 + 3][r] = v.w;
        }
#pragma unroll
        for (int it = 0; it < 2; it++) {
            int i = tid + it * 256;
            int c4 = i & 15, k = i >> 4;
            float4 v = *(const float4*)(W + (size_t)(kc + k) * HD + c4 * 4);
            float2* wp = (float2*)&sWd[k][c4 * 8];
            wp[0] = make_float2(v.x, v.x);
            wp[1] = make_float2(v.y, v.y);
            wp[2] = make_float2(v.z, v.z);
            wp[3] = make_float2(v.w, v.w);
        }
        __syncthreads();
#pragma unroll 8
        for (int k = 0; k < 32; k++) {
            ulonglong2 a01 = *(const ulonglong2*)&sAT[k][rg * 8];
            ulonglong2 a23 = *(const ulonglong2*)&sAT[k][rg * 8 + 4];
            ulonglong2 w01 = *(const ulonglong2*)&sWd[k][cg * 8];
            ulonglong2 w23 = *(const ulonglong2*)&sWd[k][cg * 8 + 4];
            acc[0][0] = fma2(a01.x, w01.x, acc[0][0]);
            acc[0][1] = fma2(a01.x, w01.y, acc[0][1]);
            acc[0][2] = fma2(a01.x, w23.x, acc[0][2]);
            acc[0][3] = fma2(a01.x, w23.y, acc[0][3]);
            acc[1][0] = fma2(a01.y, w01.x, acc[1][0]);
            acc[1][1] = fma2(a01.y, w01.y, acc[1][1]);
            acc[1][2] = fma2(a01.y, w23.x, acc[1][2]);
            acc[1][3] = fma2(a01.y, w23.y, acc[1][3]);
            acc[2][0] = fma2(a23.x, w01.x, acc[2][0]);
            acc[2][1] = fma2(a23.x, w01.y, acc[2][1]);
            acc[2][2] = fma2(a23.x, w23.x, acc[2][2]);
            acc[2][3] = fma2(a23.x, w23.y, acc[2][3]);
            acc[3][0] = fma2(a23.y, w01.x, acc[3][0]);
            acc[3][1] = fma2(a23.y, w01.y, acc[3][1]);
            acc[3][2] = fma2(a23.y, w23.x, acc[3][2]);
            acc[3][3] = fma2(a23.y, w23.y, acc[3][3]);
        }
        __syncthreads();
    }
#pragma unroll
    for (int rp = 0; rp < 4; rp++) {
        float2 c0 = asf2(acc[rp][0]);
        float2 c1 = asf2(acc[rp][1]);
        float2 c2 = asf2(acc[rp][2]);
        float2 c3 = asf2(acc[rp][3]);
        int row0 = rb + rg * 8 + rp * 2;
        if (row0 < NN)
            *(float4*)(O + (size_t)row0 * HD + cg * 4) =
                make_float4(c0.x, c1.x, c2.x, c3.x);
        if (row0 + 1 < NN)
            *(float4*)(O + (size_t)(row0 + 1) * HD + cg * 4) =
                make_float4(c0.y, c1.y, c2.y, c3.y);
    }
}

// ---------------------------------------------------------------------------
// CSR gather: 16 threads/node, 4-edge unroll with float4 edge loads,
// 4 independent accumulators, self-loop + bias + relu fused.
__global__ void __launch_bounds__(256) k_gather(const float* __restrict__ t,
                                                float* __restrict__ h,
                                                const float* __restrict__ b,
                                                int relu) {
    int node = blockIdx.x * 16 + (threadIdx.x >> 4);
    int q = threadIdx.x & 15;
    if (node >= NN) return;
    const float4* tv = (const float4*)t;

    float di = g_dinv[node];
    float4 sv = tv[(size_t)node * 16 + q];
    float di2 = di * di;
    float4 a0 = make_float4(sv.x * di2, sv.y * di2, sv.z * di2, sv.w * di2);
    float4 a1 = make_float4(0.f, 0.f, 0.f, 0.f);
    float4 a2 = make_float4(0.f, 0.f, 0.f, 0.f);
    float4 a3 = make_float4(0.f, 0.f, 0.f, 0.f);

    int beg = g_off[node], end = g_off[node + 1];
    int i = beg;
    // align to even index for float4 edge loads
    if ((i & 1) && i < end) {
        float2 e = __ldg(&g_edge[i]);
        float4 v = tv[(size_t)__float_as_int(e.x) * 16 + q];
        a0.x += e.y * v.x; a0.y += e.y * v.y; a0.z += e.y * v.z; a0.w += e.y * v.w;
        i++;
    }
    for (; i + 4 <= end; i += 4) {
        float4 e01 = __ldg((const float4*)&g_edge[i]);      // {s0,n0,s1,n1}
        float4 e23 = __ldg((const float4*)&g_edge[i + 2]);  // {s2,n2,s3,n3}
        float4 v0 = tv[(size_t)__float_as_int(e01.x) * 16 + q];
        float4 v1 = tv[(size_t)__float_as_int(e01.z) * 16 + q];
        float4 v2 = tv[(size_t)__float_as_int(e23.x) * 16 + q];
        float4 v3 = tv[(size_t)__float_as_int(e23.z) * 16 + q];
        a0.x += e01.y * v0.x; a0.y += e01.y * v0.y; a0.z += e01.y * v0.z; a0.w += e01.y * v0.w;
        a1.x += e01.w * v1.x; a1.y += e01.w * v1.y; a1.z += e01.w * v1.z; a1.w += e01.w * v1.w;
        a2.x += e23.y * v2.x; a2.y += e23.y * v2.y; a2.z += e23.y * v2.z; a2.w += e23.y * v2.w;
        a3.x += e23.w * v3.x; a3.y += e23.w * v3.y; a3.z += e23.w * v3.z; a3.w += e23.w * v3.w;
    }
    for (; i < end; i++) {
        float2 e = __ldg(&g_edge[i]);
        float4 v = tv[(size_t)__float_as_int(e.x) * 16 + q];
        a0.x += e.y * v.x; a0.y += e.y * v.y; a0.z += e.y * v.z; a0.w += e.y * v.w;
    }
    a0.x += a1.x + a2.x + a3.x;
    a0.y += a1.y + a2.y + a3.y;
    a0.z += a1.z + a2.z + a3.z;
    a0.w += a1.w + a2.w + a3.w;

    float4 bb = ((const float4*)b)[q];
    a0.x += bb.x; a0.y += bb.y; a0.z += bb.z; a0.w += bb.w;
    if (relu) {
        a0.x = fmaxf(a0.x, 0.f);
        a0.y = fmaxf(a0.y, 0.f);
        a0.z = fmaxf(a0.z, 0.f);
        a0.w = fmaxf(a0.w, 0.f);
    }
    ((float4*)h)[(size_t)node * 16 + q] = a0;
}

// ---------------------------------------------------------------------------
// Fused: L2-normalize row -> out_h, then logits -> log_softmax -> out_pred.
__global__ void k_normpred(const float* __restrict__ h, float* __restrict__ out_h,
                           const float* __restrict__ W3, const float* __restrict__ b3,
                           float* __restrict__ pred) {
    __shared__ float sW[HD * CD];
    __shared__ float sb[CD];
    for (int i = threadIdx.x; i < HD * CD; i += blockDim.x) sW[i] = W3[i];
    if (threadIdx.x < CD) sb[threadIdx.x] = b3[threadIdx.x];
    __syncthreads();
    int n = blockIdx.x * blockDim.x + threadIdx.x;
    if (n >= NN) return;

    const float4* hv = (const float4*)(h + (size_t)n * HD);
    float4 r[16];
    float ss = 0.f;
#pragma unroll
    for (int i = 0; i < 16; i++) {
        float4 v = hv[i];
        r[i] = v;
        ss += v.x * v.x + v.y * v.y + v.z * v.z + v.w * v.w;
    }
    float sc = 1.0f / fmaxf(sqrtf(ss), 1e-12f);

    float z[CD];
#pragma unroll
    for (int c = 0; c < CD; c++) z[c] = sb[c];
    float* oo = out_h + (size_t)n * HD;
#pragma unroll
    for (int k4 = 0; k4 < 16; k4++) {
        float4 v = r[k4];
        v.x *= sc; v.y *= sc; v.z *= sc; v.w *= sc;
        oo[k4 * 4 + 0] = v.x;
        oo[k4 * 4 + 1] = v.y;
        oo[k4 * 4 + 2] = v.z;
        oo[k4 * 4 + 3] = v.w;
        const float* w0 = &sW[(k4 * 4 + 0) * CD];
        const float* w1 = &sW[(k4 * 4 + 1) * CD];
        const float* w2 = &sW[(k4 * 4 + 2) * CD];
        const float* w3 = &sW[(k4 * 4 + 3) * CD];
#pragma unroll
        for (int c = 0; c < CD; c++)
            z[c] += v.x * w0[c] + v.y * w1[c] + v.z * w2[c] + v.w * w3[c];
    }
    float m = z[0];
#pragma unroll
    for (int c = 1; c < CD; c++) m = fmaxf(m, z[c]);
    float se = 0.f;
#pragma unroll
    for (int c = 0; c < CD; c++) se += expf(z[c] - m);
    float lse = m + logf(se);
    float* po = pred + (size_t)n * CD;
#pragma unroll
    for (int c = 0; c < CD; c++) po[c] = z[c] - lse;
}

// NLL loss over train indices — single block, deterministic reduce
__global__ void k_loss(const float* __restrict__ pred, const int* __restrict__ labels,
                       const int* __restrict__ tidx, float* __restrict__ out) {
    __shared__ float sred[256];
    float s = 0.f;
    for (int i = threadIdx.x; i < NTR; i += 256) {
        int idx = tidx[i];
        s += pred[(size_t)idx * CD + labels[idx]];
    }
    sred[threadIdx.x] = s;
    __syncthreads();
    for (int o = 128; o > 0; o >>= 1) {
        if (threadIdx.x < o) sred[threadIdx.x] += sred[threadIdx.x + o];
        __syncthreads();
    }
    if (threadIdx.x == 0) out[0] = -sred[0] / (float)NTR;
}

// ---------------------------------------------------------------------------
extern "C" void kernel_launch(void* const* d_in, const int* in_sizes, int n_in,
                              void* d_out, int out_size) {
    const float* feats  = (const float*)d_in[0];
    const float* W1     = (const float*)d_in[1];
    const float* b1     = (const float*)d_in[2];
    const float* W2     = (const float*)d_in[3];
    const float* b2     = (const float*)d_in[4];
    const float* W3     = (const float*)d_in[5];
    const float* b3     = (const float*)d_in[6];
    const int*   edges  = (const int*)d_in[7];
    const int*   labels = (const int*)d_in[8];
    const int*   tidx   = (const int*)d_in[9];

    float* out      = (float*)d_out;
    float* out_pred = out + 1;
    float* out_h    = out + 1 + (size_t)NN * CD;

    float* t_ptr;  cudaGetSymbolAddress((void**)&t_ptr, g_t);
    float* h_ptr;  cudaGetSymbolAddress((void**)&h_ptr, g_h);
    int*   deg_ptr; cudaGetSymbolAddress((void**)&deg_ptr, g_deg);

    const int* src = edges;        // edge_list[0]
    const int* dst = edges + EE;   // edge_list[1]

    // Lazily-created side stream + events (created once, outside capture,
    // during the harness's correctness run; reused in the captured graph).
    static cudaStream_t s2 = 0;
    static cudaEvent_t evFork = 0, evJoin = 0;
    if (s2 == 0) {
        cudaStreamCreate(&s2);
        cudaEventCreateWithFlags(&evFork, cudaEventDisableTiming);
        cudaEventCreateWithFlags(&evJoin, cudaEventDisableTiming);
    }

    const int gemm_blocks = (NN + 127) / 128;
    const int gath_blocks = (NN + 15) / 16;

    // Fork: layer-0 GEMM on side stream, CSR build on main stream.
    cudaEventRecord(evFork, 0);
    cudaStreamWaitEvent(s2, evFork, 0);
    k_gemm<IND><<<gemm_blocks, 256, 0, s2>>>(feats, W1, t_ptr);
    cudaEventRecord(evJoin, s2);

    // ---- CSR build (main stream, overlapped with the GEMM)
    k_zero_i<<<(NN + 255) / 256, 256>>>(deg_ptr, NN);
    k_deg<<<(EE + 255) / 256, 256>>>(dst);
    k_scanA<<<SCB, 256>>>();
    k_scanB<<<1, 256>>>();
    k_scanC<<<SCB, 256>>>();
    k_fill<<<(EE + 255) / 256, 256>>>(src, dst);

    // Join: gather needs both the GEMM output and the CSR.
    cudaStreamWaitEvent(0, evJoin, 0);

    // Layer 0 aggregate (no relu)
    k_gather<<<gath_blocks, 256>>>(t_ptr, h_ptr, b1, 0);

    // Hidden layers (relu)
    for (int l = 0; l < 2; l++) {
        k_gemm<HD><<<gemm_blocks, 256>>>(h_ptr, W2 + (size_t)l * HD * HD, t_ptr);
        k_gather<<<gath_blocks, 256>>>(t_ptr, h_ptr, b2 + (size_t)l * HD, 1);
    }

    // normalize + out_h + logits + log_softmax ; then nll
    k_normpred<<<(NN + 255) / 256, 256>>>(h_ptr, out_h, W3, b3, out_pred);
    k_loss<<<1, 256>>>(out_pred, labels, tidx, out);
}

// round 11
// speedup vs baseline: 1.1550x; 1.0667x over previous
#include <cuda_runtime.h>
#include <cuda_fp16.h>
#include <math.h>

#define NN   50000
#define EE   1600000
#define IND  256
#define HD   64
#define CD   16
#define NTR  5000
#define NH   (NN*HD)
#define SCB  ((NN + 255) / 256)   // 196 scan blocks
#define NPB  ((NN + 255) / 256)   // normpred blocks

// Scratch (no allocs allowed)
__device__ __align__(16) __half g_t[NH];       // x @ W  (fp16 message buffer)
__device__ __align__(16) float  g_h[NH];       // layer output (fp32)
__device__ __align__(16) float2 g_edge[EE];    // {src_as_float_bits, norm}, CSR order
__device__ float g_dinv[NN];
__device__ int   g_deg[NN];                    // zero-init; self-restored by k_scanA
__device__ int   g_off[NN + 1];
__device__ int   g_cur[NN];
__device__ int   g_bsum[SCB];
__device__ unsigned g_ctr;                     // zero-init; wraps back to 0

// ---------------------------------------------------------------------------
__device__ __forceinline__ unsigned long long fma2(unsigned long long a,
                                                   unsigned long long b,
                                                   unsigned long long c) {
    unsigned long long d;
    asm("fma.rn.f32x2 %0, %1, %2, %3;" : "=l"(d) : "l"(a), "l"(b), "l"(c));
    return d;
}
union U64F2 { unsigned long long u; float2 f; };
__device__ __forceinline__ float2 asf2(unsigned long long u) {
    U64F2 t; t.u = u; return t.f;
}

// ---------------------------------------------------------------------------
__global__ void k_deg(const int* __restrict__ dst) {
    int e = blockIdx.x * blockDim.x + threadIdx.x;
    if (e < EE) atomicAdd(&g_deg[dst[e]], 1);
}

// Phase A: per-block exclusive scan (+ dinv compute, + self-restoring deg zero)
__global__ void k_scanA() {
    __shared__ int ss[256];
    int t = threadIdx.x;
    int idx = blockIdx.x * 256 + t;
    int d = 0;
    if (idx < NN) {
        d = g_deg[idx];
        g_deg[idx] = 0;                        // restore for next call
        g_dinv[idx] = rsqrtf((float)d + 1.0f); // +1 self-loop
    }
    ss[t] = d;
    __syncthreads();
#pragma unroll
    for (int o = 1; o < 256; o <<= 1) {
        int v = (t >= o) ? ss[t - o] : 0;
        __syncthreads();
        ss[t] += v;
        __syncthreads();
    }
    int inc = ss[t];
    if (idx < NN) g_off[idx] = inc - d;
    if (t == 255) g_bsum[blockIdx.x] = inc;
}
__global__ void k_scanB() {
    __shared__ int ss[SCB];
    int t = threadIdx.x;
    int v = (t < SCB) ? g_bsum[t] : 0;
    if (t < SCB) ss[t] = v;
    __syncthreads();
    for (int o = 1; o < SCB; o <<= 1) {
        int u = (t >= o && t < SCB) ? ss[t - o] : 0;
        __syncthreads();
        if (t < SCB) ss[t] += u;
        __syncthreads();
    }
    if (t < SCB) g_bsum[t] = ss[t] - v;
}
__global__ void k_scanC() {
    int idx = blockIdx.x * 256 + threadIdx.x;
    if (idx < NN) {
        int o = g_off[idx] + g_bsum[blockIdx.x];
        g_off[idx] = o;
        g_cur[idx] = o;
    }
    if (idx == 0) g_off[NN] = EE;
}

// Bucket edges by dst; one 8B packed store per edge.
__global__ void k_fill(const int* __restrict__ src, const int* __restrict__ dst) {
    int e = blockIdx.x * blockDim.x + threadIdx.x;
    if (e >= EE) return;
    int s = src[e], d = dst[e];
    int pos = atomicAdd(&g_cur[d], 1);
    g_edge[pos] = make_float2(__int_as_float(s), g_dinv[s] * g_dinv[d]);
}

// ---------------------------------------------------------------------------
// O[N,64] = A[N,K] @ W[K,64], fp32 compute, fp16 output.
// 128x64 tile, 256 threads, K-chunk 32, f32x2 FMA.
template <int K>
__global__ void __launch_bounds__(256) k_gemm(const float* __restrict__ A,
                                              const float* __restrict__ W,
                                              __half* __restrict__ O) {
    __shared__ __align__(16) float sAT[32][132];   // [k][row], padded
    __shared__ __align__(16) float sWd[32][136];   // [k][2*col] dup pairs, padded
    const int tid = threadIdx.x;
    const int rg = tid & 15;
    const int cg = tid >> 4;
    const int rb = blockIdx.x * 128;

    unsigned long long acc[4][4];
#pragma unroll
    for (int i = 0; i < 4; i++)
#pragma unroll
        for (int j = 0; j < 4; j++) acc[i][j] = 0ull;

    for (int kc = 0; kc < K; kc += 32) {
#pragma unroll
        for (int it = 0; it < 4; it++) {
            int i = tid + it * 256;
            int r = i >> 3, k4 = i & 7;
            int row = rb + r;
            float4 v = (row < NN)
                ? *(const float4*)(A + (size_t)row * K + kc + k4 * 4)
                : make_float4(0.f, 0.f, 0.f, 0.f);
            sAT[k4 * 4 + 0][r] = v.x;
            sAT[k4 * 4 + 1][r] = v.y;
            sAT[k4 * 4 + 2][r] = v.z;
            sAT[k4 * 4 + 3][r] = v.w;
        }
#pragma unroll
        for (int it = 0; it < 2; it++) {
            int i = tid + it * 256;
            int c4 = i & 15, k = i >> 4;
            float4 v = *(const float4*)(W + (size_t)(kc + k) * HD + c4 * 4);
            float2* wp = (float2*)&sWd[k][c4 * 8];
            wp[0] = make_float2(v.x, v.x);
            wp[1] = make_float2(v.y, v.y);
            wp[2] = make_float2(v.z, v.z);
            wp[3] = make_float2(v.w, v.w);
        }
        __syncthreads();
#pragma unroll 8
        for (int k = 0; k < 32; k++) {
            ulonglong2 a01 = *(const ulonglong2*)&sAT[k][rg * 8];
            ulonglong2 a23 = *(const ulonglong2*)&sAT[k][rg * 8 + 4];
            ulonglong2 w01 = *(const ulonglong2*)&sWd[k][cg * 8];
            ulonglong2 w23 = *(const ulonglong2*)&sWd[k][cg * 8 + 4];
            acc[0][0] = fma2(a01.x, w01.x, acc[0][0]);
            acc[0][1] = fma2(a01.x, w01.y, acc[0][1]);
            acc[0][2] = fma2(a01.x, w23.x, acc[0][2]);
            acc[0][3] = fma2(a01.x, w23.y, acc[0][3]);
            acc[1][0] = fma2(a01.y, w01.x, acc[1][0]);
            acc[1][1] = fma2(a01.y, w01.y, acc[1][1]);
            acc[1][2] = fma2(a01.y, w23.x, acc[1][2]);
            acc[1][3] = fma2(a01.y, w23.y, acc[1][3]);
            acc[2][0] = fma2(a23.x, w01.x, acc[2][0]);
            acc[2][1] = fma2(a23.x, w01.y, acc[2][1]);
            acc[2][2] = fma2(a23.x, w23.x, acc[2][2]);
            acc[2][3] = fma2(a23.x, w23.y, acc[2][3]);
            acc[3][0] = fma2(a23.y, w01.x, acc[3][0]);
            acc[3][1] = fma2(a23.y, w01.y, acc[3][1]);
            acc[3][2] = fma2(a23.y, w23.x, acc[3][2]);
            acc[3][3] = fma2(a23.y, w23.y, acc[3][3]);
        }
        __syncthreads();
    }
#pragma unroll
    for (int rp = 0; rp < 4; rp++) {
        float2 c0 = asf2(acc[rp][0]);
        float2 c1 = asf2(acc[rp][1]);
        float2 c2 = asf2(acc[rp][2]);
        float2 c3 = asf2(acc[rp][3]);
        int row0 = rb + rg * 8 + rp * 2;
        if (row0 < NN) {
            union { uint2 u; __half2 h[2]; } pk;
            pk.h[0] = __floats2half2_rn(c0.x, c1.x);
            pk.h[1] = __floats2half2_rn(c2.x, c3.x);
            *(uint2*)(O + (size_t)row0 * HD + cg * 4) = pk.u;
        }
        if (row0 + 1 < NN) {
            union { uint2 u; __half2 h[2]; } pk;
            pk.h[0] = __floats2half2_rn(c0.y, c1.y);
            pk.h[1] = __floats2half2_rn(c2.y, c3.y);
            *(uint2*)(O + (size_t)(row0 + 1) * HD + cg * 4) = pk.u;
        }
    }
}

// ---------------------------------------------------------------------------
// CSR gather: 16 lanes/node, lane q owns features 4q..4q+3 (8B fp16 per lane
// per row), 4-edge unroll, fp32 accumulate, self-loop + bias + relu fused.
__global__ void __launch_bounds__(256) k_gather(const __half* __restrict__ t,
                                                float* __restrict__ h,
                                                const float* __restrict__ b,
                                                int relu) {
    int node = blockIdx.x * 16 + (threadIdx.x >> 4);
    int q = threadIdx.x & 15;
    if (node >= NN) return;
    const uint2* tv = (const uint2*)t;   // 16 uint2 per 64-half row

    float di = g_dinv[node];
    float di2 = di * di;
    uint2 sr = __ldg(&tv[(size_t)node * 16 + q]);
    float2 s0 = __half22float2(*(__half2*)&sr.x);
    float2 s1 = __half22float2(*(__half2*)&sr.y);
    float4 a0 = make_float4(s0.x * di2, s0.y * di2, s1.x * di2, s1.y * di2);
    float4 a1 = make_float4(0.f, 0.f, 0.f, 0.f);
    float4 a2 = make_float4(0.f, 0.f, 0.f, 0.f);
    float4 a3 = make_float4(0.f, 0.f, 0.f, 0.f);

    int beg = g_off[node], end = g_off[node + 1];
    int i = beg;
    if ((i & 1) && i < end) {   // align for float4 edge loads
        float2 e = __ldg(&g_edge[i]);
        uint2 rv = __ldg(&tv[(size_t)__float_as_int(e.x) * 16 + q]);
        float2 f0 = __half22float2(*(__half2*)&rv.x);
        float2 f1 = __half22float2(*(__half2*)&rv.y);
        a0.x += e.y * f0.x; a0.y += e.y * f0.y; a0.z += e.y * f1.x; a0.w += e.y * f1.y;
        i++;
    }
    for (; i + 4 <= end; i += 4) {
        float4 e01 = __ldg((const float4*)&g_edge[i]);      // {s0,n0,s1,n1}
        float4 e23 = __ldg((const float4*)&g_edge[i + 2]);  // {s2,n2,s3,n3}
        uint2 r0 = __ldg(&tv[(size_t)__float_as_int(e01.x) * 16 + q]);
        uint2 r1 = __ldg(&tv[(size_t)__float_as_int(e01.z) * 16 + q]);
        uint2 r2 = __ldg(&tv[(size_t)__float_as_int(e23.x) * 16 + q]);
        uint2 r3 = __ldg(&tv[(size_t)__float_as_int(e23.z) * 16 + q]);
        float2 f0a = __half22float2(*(__half2*)&r0.x), f0b = __half22float2(*(__half2*)&r0.y);
        float2 f1a = __half22float2(*(__half2*)&r1.x), f1b = __half22float2(*(__half2*)&r1.y);
        float2 f2a = __half22float2(*(__half2*)&r2.x), f2b = __half22float2(*(__half2*)&r2.y);
        float2 f3a = __half22float2(*(__half2*)&r3.x), f3b = __half22float2(*(__half2*)&r3.y);
        a0.x += e01.y * f0a.x; a0.y += e01.y * f0a.y; a0.z += e01.y * f0b.x; a0.w += e01.y * f0b.y;
        a1.x += e01.w * f1a.x; a1.y += e01.w * f1a.y; a1.z += e01.w * f1b.x; a1.w += e01.w * f1b.y;
        a2.x += e23.y * f2a.x; a2.y += e23.y * f2a.y; a2.z += e23.y * f2b.x; a2.w += e23.y * f2b.y;
        a3.x += e23.w * f3a.x; a3.y += e23.w * f3a.y; a3.z += e23.w * f3b.x; a3.w += e23.w * f3b.y;
    }
    for (; i < end; i++) {
        float2 e = __ldg(&g_edge[i]);
        uint2 rv = __ldg(&tv[(size_t)__float_as_int(e.x) * 16 + q]);
        float2 f0 = __half22float2(*(__half2*)&rv.x);
        float2 f1 = __half22float2(*(__half2*)&rv.y);
        a0.x += e.y * f0.x; a0.y += e.y * f0.y; a0.z += e.y * f1.x; a0.w += e.y * f1.y;
    }
    a0.x += a1.x + a2.x + a3.x;
    a0.y += a1.y + a2.y + a3.y;
    a0.z += a1.z + a2.z + a3.z;
    a0.w += a1.w + a2.w + a3.w;

    float4 bb = ((const float4*)b)[q];
    a0.x += bb.x; a0.y += bb.y; a0.z += bb.z; a0.w += bb.w;
    if (relu) {
        a0.x = fmaxf(a0.x, 0.f);
        a0.y = fmaxf(a0.y, 0.f);
        a0.z = fmaxf(a0.z, 0.f);
        a0.w = fmaxf(a0.w, 0.f);
    }
    ((float4*)h)[(size_t)node * 16 + q] = a0;
}

// ---------------------------------------------------------------------------
// Fused: L2-normalize -> out_h, logits -> log_softmax -> out_pred,
// and NLL loss in the last-finishing block (threadfence + wrap counter).
__global__ void k_normpred(const float* __restrict__ h, float* __restrict__ out_h,
                           const float* __restrict__ W3, const float* __restrict__ b3,
                           float* __restrict__ pred,
                           const int* __restrict__ labels, const int* __restrict__ tidx,
                           float* __restrict__ out) {
    __shared__ float sW[HD * CD];
    __shared__ float sb[CD];
    __shared__ int s_last;
    for (int i = threadIdx.x; i < HD * CD; i += blockDim.x) sW[i] = W3[i];
    if (threadIdx.x < CD) sb[threadIdx.x] = b3[threadIdx.x];
    __syncthreads();
    int n = blockIdx.x * blockDim.x + threadIdx.x;

    if (n < NN) {
        const float4* hv = (const float4*)(h + (size_t)n * HD);
        float4 r[16];
        float ss = 0.f;
#pragma unroll
        for (int i = 0; i < 16; i++) {
            float4 v = hv[i];
            r[i] = v;
            ss += v.x * v.x + v.y * v.y + v.z * v.z + v.w * v.w;
        }
        float sc = 1.0f / fmaxf(sqrtf(ss), 1e-12f);

        float z[CD];
#pragma unroll
        for (int c = 0; c < CD; c++) z[c] = sb[c];
        float* oo = out_h + (size_t)n * HD;
#pragma unroll
        for (int k4 = 0; k4 < 16; k4++) {
            float4 v = r[k4];
            v.x *= sc; v.y *= sc; v.z *= sc; v.w *= sc;
            oo[k4 * 4 + 0] = v.x;
            oo[k4 * 4 + 1] = v.y;
            oo[k4 * 4 + 2] = v.z;
            oo[k4 * 4 + 3] = v.w;
            const float* w0 = &sW[(k4 * 4 + 0) * CD];
            const float* w1 = &sW[(k4 * 4 + 1) * CD];
            const float* w2 = &sW[(k4 * 4 + 2) * CD];
            const float* w3 = &sW[(k4 * 4 + 3) * CD];
#pragma unroll
            for (int c = 0; c < CD; c++)
                z[c] += v.x * w0[c] + v.y * w1[c] + v.z * w2[c] + v.w * w3[c];
        }
        float m = z[0];
#pragma unroll
        for (int c = 1; c < CD; c++) m = fmaxf(m, z[c]);
        float se = 0.f;
#pragma unroll
        for (int c = 0; c < CD; c++) se += expf(z[c] - m);
        float lse = m + logf(se);
        float* po = pred + (size_t)n * CD;
#pragma unroll
        for (int c = 0; c < CD; c++) po[c] = z[c] - lse;
    }

    // Last-block NLL loss (self-restoring wrap counter).
    __threadfence();
    __syncthreads();
    if (threadIdx.x == 0) {
        unsigned tk = atomicInc(&g_ctr, NPB - 1);
        s_last = (tk == NPB - 1);
    }
    __syncthreads();
    if (s_last) {
        __shared__ float sred[256];
        float s = 0.f;
        for (int i = threadIdx.x; i < NTR; i += 256) {
            int idx = tidx[i];
            s += pred[(size_t)idx * CD + labels[idx]];
        }
        sred[threadIdx.x] = s;
        __syncthreads();
        for (int o = 128; o > 0; o >>= 1) {
            if (threadIdx.x < o) sred[threadIdx.x] += sred[threadIdx.x + o];
            __syncthreads();
        }
        if (threadIdx.x == 0) out[0] = -sred[0] / (float)NTR;
    }
}

// ---------------------------------------------------------------------------
extern "C" void kernel_launch(void* const* d_in, const int* in_sizes, int n_in,
                              void* d_out, int out_size) {
    const float* feats  = (const float*)d_in[0];
    const float* W1     = (const float*)d_in[1];
    const float* b1     = (const float*)d_in[2];
    const float* W2     = (const float*)d_in[3];
    const float* b2     = (const float*)d_in[4];
    const float* W3     = (const float*)d_in[5];
    const float* b3     = (const float*)d_in[6];
    const int*   edges  = (const int*)d_in[7];
    const int*   labels = (const int*)d_in[8];
    const int*   tidx   = (const int*)d_in[9];

    float* out      = (float*)d_out;
    float* out_pred = out + 1;
    float* out_h    = out + 1 + (size_t)NN * CD;

    __half* t_ptr; cudaGetSymbolAddress((void**)&t_ptr, g_t);
    float*  h_ptr; cudaGetSymbolAddress((void**)&h_ptr, g_h);

    const int* src = edges;        // edge_list[0]
    const int* dst = edges + EE;   // edge_list[1]

    static cudaStream_t s2 = 0;
    static cudaEvent_t evFork = 0, evJoin = 0;
    if (s2 == 0) {
        cudaStreamCreate(&s2);
        cudaEventCreateWithFlags(&evFork, cudaEventDisableTiming);
        cudaEventCreateWithFlags(&evJoin, cudaEventDisableTiming);
    }

    const int gemm_blocks = (NN + 127) / 128;
    const int gath_blocks = (NN + 15) / 16;

    // Fork: layer-0 GEMM on side stream, CSR build on main stream.
    cudaEventRecord(evFork, 0);
    cudaStreamWaitEvent(s2, evFork, 0);
    k_gemm<IND><<<gemm_blocks, 256, 0, s2>>>(feats, W1, t_ptr);
    cudaEventRecord(evJoin, s2);

    // ---- CSR build (g_deg arrives zeroed: static init / scanA restore)
    k_deg<<<(EE + 255) / 256, 256>>>(dst);
    k_scanA<<<SCB, 256>>>();
    k_scanB<<<1, 256>>>();
    k_scanC<<<SCB, 256>>>();
    k_fill<<<(EE + 255) / 256, 256>>>(src, dst);

    cudaStreamWaitEvent(0, evJoin, 0);

    // Layer 0 aggregate (no relu)
    k_gather<<<gath_blocks, 256>>>(t_ptr, h_ptr, b1, 0);

    // Hidden layers (relu)
    for (int l = 0; l < 2; l++) {
        k_gemm<HD><<<gemm_blocks, 256>>>(h_ptr, W2 + (size_t)l * HD * HD, t_ptr);
        k_gather<<<gath_blocks, 256>>>(t_ptr, h_ptr, b2 + (size_t)l * HD, 1);
    }

    // normalize + out_h + logits + log_softmax + fused loss
    k_normpred<<<NPB, 256>>>(h_ptr, out_h, W3, b3, out_pred, labels, tidx, out);
}

// round 12
// speedup vs baseline: 1.1684x; 1.0116x over previous
#include <cuda_runtime.h>
#include <cuda_fp16.h>
#include <math.h>

#define NN   50000
#define EE   1600000
#define IND  256
#define HD   64
#define CD   16
#define NTR  5000
#define NH   (NN*HD)
#define SCB  ((NN + 255) / 256)   // 196 scan blocks
#define NPB  ((NN + 255) / 256)   // normpred blocks

// Scratch (no allocs allowed)
__device__ __align__(16) __half g_t[NH];       // x @ W  (fp16 message buffer)
__device__ __align__(16) float  g_h[NH];       // layer output (fp32)
__device__ __align__(16) float2 g_edge[EE];    // {src_as_float_bits, norm}, CSR order
__device__ float g_dinv[NN];
__device__ int   g_deg[NN];                    // zero-init; self-restored by k_scanA
__device__ int   g_off[NN + 1];
__device__ int   g_cur[NN];
__device__ int   g_bsum[SCB];
__device__ unsigned g_ctr;                     // zero-init; wraps back to 0 (normpred)
__device__ unsigned g_ctr2;                    // zero-init; wraps back to 0 (scanA)

// ---------------------------------------------------------------------------
__device__ __forceinline__ unsigned long long fma2(unsigned long long a,
                                                   unsigned long long b,
                                                   unsigned long long c) {
    unsigned long long d;
    asm("fma.rn.f32x2 %0, %1, %2, %3;" : "=l"(d) : "l"(a), "l"(b), "l"(c));
    return d;
}
union U64F2 { unsigned long long u; float2 f; };
__device__ __forceinline__ float2 asf2(unsigned long long u) {
    U64F2 t; t.u = u; return t.f;
}

// ---------------------------------------------------------------------------
__global__ void k_deg(const int* __restrict__ dst) {
    int e = blockIdx.x * blockDim.x + threadIdx.x;
    if (e < EE) atomicAdd(&g_deg[dst[e]], 1);
}

// Per-block exclusive scan + dinv + self-restoring deg zero.
// Last-finishing block also scans the 196 block sums (fused scanB).
__global__ void k_scanA() {
    __shared__ int ss[256];
    __shared__ int s_last;
    int t = threadIdx.x;
    int idx = blockIdx.x * 256 + t;
    int d = 0;
    if (idx < NN) {
        d = g_deg[idx];
        g_deg[idx] = 0;                        // restore for next call
        g_dinv[idx] = rsqrtf((float)d + 1.0f); // +1 self-loop
    }
    ss[t] = d;
    __syncthreads();
#pragma unroll
    for (int o = 1; o < 256; o <<= 1) {
        int v = (t >= o) ? ss[t - o] : 0;
        __syncthreads();
        ss[t] += v;
        __syncthreads();
    }
    int inc = ss[t];
    if (idx < NN) g_off[idx] = inc - d;
    if (t == 255) g_bsum[blockIdx.x] = inc;

    // fused scanB in the last-finishing block
    __threadfence();
    __syncthreads();
    if (t == 0) {
        unsigned tk = atomicInc(&g_ctr2, SCB - 1);
        s_last = (tk == SCB - 1);
    }
    __syncthreads();
    if (s_last) {
        int v = (t < SCB) ? g_bsum[t] : 0;
        ss[t] = v;
        __syncthreads();
#pragma unroll
        for (int o = 1; o < 256; o <<= 1) {
            int u = (t >= o) ? ss[t - o] : 0;
            __syncthreads();
            ss[t] += u;
            __syncthreads();
        }
        if (t < SCB) g_bsum[t] = ss[t] - v;    // exclusive block offsets
    }
}
__global__ void k_scanC() {
    int idx = blockIdx.x * 256 + threadIdx.x;
    if (idx < NN) {
        int o = g_off[idx] + g_bsum[blockIdx.x];
        g_off[idx] = o;
        g_cur[idx] = o;
    }
    if (idx == 0) g_off[NN] = EE;
}

// Bucket edges by dst; one 8B packed store per edge.
__global__ void k_fill(const int* __restrict__ src, const int* __restrict__ dst) {
    int e = blockIdx.x * blockDim.x + threadIdx.x;
    if (e >= EE) return;
    int s = src[e], d = dst[e];
    int pos = atomicAdd(&g_cur[d], 1);
    g_edge[pos] = make_float2(__int_as_float(s), g_dinv[s] * g_dinv[d]);
}

// ---------------------------------------------------------------------------
// O[N,64] = A[N,K] @ W[K,64], fp32 compute, fp16 output.
template <int K>
__global__ void __launch_bounds__(256) k_gemm(const float* __restrict__ A,
                                              const float* __restrict__ W,
                                              __half* __restrict__ O) {
    __shared__ __align__(16) float sAT[32][132];
    __shared__ __align__(16) float sWd[32][136];
    const int tid = threadIdx.x;
    const int rg = tid & 15;
    const int cg = tid >> 4;
    const int rb = blockIdx.x * 128;

    unsigned long long acc[4][4];
#pragma unroll
    for (int i = 0; i < 4; i++)
#pragma unroll
        for (int j = 0; j < 4; j++) acc[i][j] = 0ull;

    for (int kc = 0; kc < K; kc += 32) {
#pragma unroll
        for (int it = 0; it < 4; it++) {
            int i = tid + it * 256;
            int r = i >> 3, k4 = i & 7;
            int row = rb + r;
            float4 v = (row < NN)
                ? *(const float4*)(A + (size_t)row * K + kc + k4 * 4)
                : make_float4(0.f, 0.f, 0.f, 0.f);
            sAT[k4 * 4 + 0][r] = v.x;
            sAT[k4 * 4 + 1][r] = v.y;
            sAT[k4 * 4 + 2][r] = v.z;
            sAT[k4 * 4 + 3][r] = v.w;
        }
#pragma unroll
        for (int it = 0; it < 2; it++) {
            int i = tid + it * 256;
            int c4 = i & 15, k = i >> 4;
            float4 v = *(const float4*)(W + (size_t)(kc + k) * HD + c4 * 4);
            float2* wp = (float2*)&sWd[k][c4 * 8];
            wp[0] = make_float2(v.x, v.x);
            wp[1] = make_float2(v.y, v.y);
            wp[2] = make_float2(v.z, v.z);
            wp[3] = make_float2(v.w, v.w);
        }
        __syncthreads();
#pragma unroll 8
        for (int k = 0; k < 32; k++) {
            ulonglong2 a01 = *(const ulonglong2*)&sAT[k][rg * 8];
            ulonglong2 a23 = *(const ulonglong2*)&sAT[k][rg * 8 + 4];
            ulonglong2 w01 = *(const ulonglong2*)&sWd[k][cg * 8];
            ulonglong2 w23 = *(const ulonglong2*)&sWd[k][cg * 8 + 4];
            acc[0][0] = fma2(a01.x, w01.x, acc[0][0]);
            acc[0][1] = fma2(a01.x, w01.y, acc[0][1]);
            acc[0][2] = fma2(a01.x, w23.x, acc[0][2]);
            acc[0][3] = fma2(a01.x, w23.y, acc[0][3]);
            acc[1][0] = fma2(a01.y, w01.x, acc[1][0]);
            acc[1][1] = fma2(a01.y, w01.y, acc[1][1]);
            acc[1][2] = fma2(a01.y, w23.x, acc[1][2]);
            acc[1][3] = fma2(a01.y, w23.y, acc[1][3]);
            acc[2][0] = fma2(a23.x, w01.x, acc[2][0]);
            acc[2][1] = fma2(a23.x, w01.y, acc[2][1]);
            acc[2][2] = fma2(a23.x, w23.x, acc[2][2]);
            acc[2][3] = fma2(a23.x, w23.y, acc[2][3]);
            acc[3][0] = fma2(a23.y, w01.x, acc[3][0]);
            acc[3][1] = fma2(a23.y, w01.y, acc[3][1]);
            acc[3][2] = fma2(a23.y, w23.x, acc[3][2]);
            acc[3][3] = fma2(a23.y, w23.y, acc[3][3]);
        }
        __syncthreads();
    }
#pragma unroll
    for (int rp = 0; rp < 4; rp++) {
        float2 c0 = asf2(acc[rp][0]);
        float2 c1 = asf2(acc[rp][1]);
        float2 c2 = asf2(acc[rp][2]);
        float2 c3 = asf2(acc[rp][3]);
        int row0 = rb + rg * 8 + rp * 2;
        if (row0 < NN) {
            union { uint2 u; __half2 h[2]; } pk;
            pk.h[0] = __floats2half2_rn(c0.x, c1.x);
            pk.h[1] = __floats2half2_rn(c2.x, c3.x);
            *(uint2*)(O + (size_t)row0 * HD + cg * 4) = pk.u;
        }
        if (row0 + 1 < NN) {
            union { uint2 u; __half2 h[2]; } pk;
            pk.h[0] = __floats2half2_rn(c0.y, c1.y);
            pk.h[1] = __floats2half2_rn(c2.y, c3.y);
            *(uint2*)(O + (size_t)(row0 + 1) * HD + cg * 4) = pk.u;
        }
    }
}

// ---------------------------------------------------------------------------
// CSR gather: 16 lanes/node, 8-edge unroll (8 outstanding row loads),
// fp32 accumulate, self-loop + bias + relu fused.
__global__ void __launch_bounds__(256) k_gather(const __half* __restrict__ t,
                                                float* __restrict__ h,
                                                const float* __restrict__ b,
                                                int relu) {
    int node = blockIdx.x * 16 + (threadIdx.x >> 4);
    int q = threadIdx.x & 15;
    if (node >= NN) return;
    const uint2* tv = (const uint2*)t;   // 16 uint2 per 64-half row

    float di = g_dinv[node];
    float di2 = di * di;
    uint2 sr = __ldg(&tv[(size_t)node * 16 + q]);
    float2 s0 = __half22float2(*(__half2*)&sr.x);
    float2 s1 = __half22float2(*(__half2*)&sr.y);
    float4 a0 = make_float4(s0.x * di2, s0.y * di2, s1.x * di2, s1.y * di2);
    float4 a1 = make_float4(0.f, 0.f, 0.f, 0.f);
    float4 a2 = make_float4(0.f, 0.f, 0.f, 0.f);
    float4 a3 = make_float4(0.f, 0.f, 0.f, 0.f);

    int beg = g_off[node], end = g_off[node + 1];
    int i = beg;
    if ((i & 1) && i < end) {   // align for float4 edge loads
        float2 e = __ldg(&g_edge[i]);
        uint2 rv = __ldg(&tv[(size_t)__float_as_int(e.x) * 16 + q]);
        float2 f0 = __half22float2(*(__half2*)&rv.x);
        float2 f1 = __half22float2(*(__half2*)&rv.y);
        a0.x += e.y * f0.x; a0.y += e.y * f0.y; a0.z += e.y * f1.x; a0.w += e.y * f1.y;
        i++;
    }
    // 8-edge main loop: 4 edge-pair loads + 8 row loads issued before use.
    for (; i + 8 <= end; i += 8) {
        float4 eA = __ldg((const float4*)&g_edge[i]);
        float4 eB = __ldg((const float4*)&g_edge[i + 2]);
        float4 eC = __ldg((const float4*)&g_edge[i + 4]);
        float4 eD = __ldg((const float4*)&g_edge[i + 6]);
        uint2 r0 = __ldg(&tv[(size_t)__float_as_int(eA.x) * 16 + q]);
        uint2 r1 = __ldg(&tv[(size_t)__float_as_int(eA.z) * 16 + q]);
        uint2 r2 = __ldg(&tv[(size_t)__float_as_int(eB.x) * 16 + q]);
        uint2 r3 = __ldg(&tv[(size_t)__float_as_int(eB.z) * 16 + q]);
        uint2 r4 = __ldg(&tv[(size_t)__float_as_int(eC.x) * 16 + q]);
        uint2 r5 = __ldg(&tv[(size_t)__float_as_int(eC.z) * 16 + q]);
        uint2 r6 = __ldg(&tv[(size_t)__float_as_int(eD.x) * 16 + q]);
        uint2 r7 = __ldg(&tv[(size_t)__float_as_int(eD.z) * 16 + q]);
        float2 fa, fb;
        fa = __half22float2(*(__half2*)&r0.x); fb = __half22float2(*(__half2*)&r0.y);
        a0.x += eA.y * fa.x; a0.y += eA.y * fa.y; a0.z += eA.y * fb.x; a0.w += eA.y * fb.y;
        fa = __half22float2(*(__half2*)&r1.x); fb = __half22float2(*(__half2*)&r1.y);
        a1.x += eA.w * fa.x; a1.y += eA.w * fa.y; a1.z += eA.w * fb.x; a1.w += eA.w * fb.y;
        fa = __half22float2(*(__half2*)&r2.x); fb = __half22float2(*(__half2*)&r2.y);
        a2.x += eB.y * fa.x; a2.y += eB.y * fa.y; a2.z += eB.y * fb.x; a2.w += eB.y * fb.y;
        fa = __half22float2(*(__half2*)&r3.x); fb = __half22float2(*(__half2*)&r3.y);
        a3.x += eB.w * fa.x; a3.y += eB.w * fa.y; a3.z += eB.w * fb.x; a3.w += eB.w * fb.y;
        fa = __half22float2(*(__half2*)&r4.x); fb = __half22float2(*(__half2*)&r4.y);
        a0.x += eC.y * fa.x; a0.y += eC.y * fa.y; a0.z += eC.y * fb.x; a0.w += eC.y * fb.y;
        fa = __half22float2(*(__half2*)&r5.x); fb = __half22float2(*(__half2*)&r5.y);
        a1.x += eC.w * fa.x; a1.y += eC.w * fa.y; a1.z += eC.w * fb.x; a1.w += eC.w * fb.y;
        fa = __half22float2(*(__half2*)&r6.x); fb = __half22float2(*(__half2*)&r6.y);
        a2.x += eD.y * fa.x; a2.y += eD.y * fa.y; a2.z += eD.y * fb.x; a2.w += eD.y * fb.y;
        fa = __half22float2(*(__half2*)&r7.x); fb = __half22float2(*(__half2*)&r7.y);
        a3.x += eD.w * fa.x; a3.y += eD.w * fa.y; a3.z += eD.w * fb.x; a3.w += eD.w * fb.y;
    }
    for (; i + 2 <= end; i += 2) {
        float4 e01 = __ldg((const float4*)&g_edge[i]);
        uint2 r0 = __ldg(&tv[(size_t)__float_as_int(e01.x) * 16 + q]);
        uint2 r1 = __ldg(&tv[(size_t)__float_as_int(e01.z) * 16 + q]);
        float2 f0a = __half22float2(*(__half2*)&r0.x), f0b = __half22float2(*(__half2*)&r0.y);
        float2 f1a = __half22float2(*(__half2*)&r1.x), f1b = __half22float2(*(__half2*)&r1.y);
        a0.x += e01.y * f0a.x; a0.y += e01.y * f0a.y; a0.z += e01.y * f0b.x; a0.w += e01.y * f0b.y;
        a1.x += e01.w * f1a.x; a1.y += e01.w * f1a.y; a1.z += e01.w * f1b.x; a1.w += e01.w * f1b.y;
    }
    if (i < end) {
        float2 e = __ldg(&g_edge[i]);
        uint2 rv = __ldg(&tv[(size_t)__float_as_int(e.x) * 16 + q]);
        float2 f0 = __half22float2(*(__half2*)&rv.x);
        float2 f1 = __half22float2(*(__half2*)&rv.y);
        a0.x += e.y * f0.x; a0.y += e.y * f0.y; a0.z += e.y * f1.x; a0.w += e.y * f1.y;
    }
    a0.x += a1.x + a2.x + a3.x;
    a0.y += a1.y + a2.y + a3.y;
    a0.z += a1.z + a2.z + a3.z;
    a0.w += a1.w + a2.w + a3.w;

    float4 bb = ((const float4*)b)[q];
    a0.x += bb.x; a0.y += bb.y; a0.z += bb.z; a0.w += bb.w;
    if (relu) {
        a0.x = fmaxf(a0.x, 0.f);
        a0.y = fmaxf(a0.y, 0.f);
        a0.z = fmaxf(a0.z, 0.f);
        a0.w = fmaxf(a0.w, 0.f);
    }
    ((float4*)h)[(size_t)node * 16 + q] = a0;
}

// ---------------------------------------------------------------------------
// Fused: L2-normalize -> out_h, logits -> log_softmax -> out_pred, last-block NLL.
__global__ void k_normpred(const float* __restrict__ h, float* __restrict__ out_h,
                           const float* __restrict__ W3, const float* __restrict__ b3,
                           float* __restrict__ pred,
                           const int* __restrict__ labels, const int* __restrict__ tidx,
                           float* __restrict__ out) {
    __shared__ float sW[HD * CD];
    __shared__ float sb[CD];
    __shared__ int s_last;
    for (int i = threadIdx.x; i < HD * CD; i += blockDim.x) sW[i] = W3[i];
    if (threadIdx.x < CD) sb[threadIdx.x] = b3[threadIdx.x];
    __syncthreads();
    int n = blockIdx.x * blockDim.x + threadIdx.x;

    if (n < NN) {
        const float4* hv = (const float4*)(h + (size_t)n * HD);
        float4 r[16];
        float ss = 0.f;
#pragma unroll
        for (int i = 0; i < 16; i++) {
            float4 v = hv[i];
            r[i] = v;
            ss += v.x * v.x + v.y * v.y + v.z * v.z + v.w * v.w;
        }
        float sc = 1.0f / fmaxf(sqrtf(ss), 1e-12f);

        float z[CD];
#pragma unroll
        for (int c = 0; c < CD; c++) z[c] = sb[c];
        float* oo = out_h + (size_t)n * HD;
#pragma unroll
        for (int k4 = 0; k4 < 16; k4++) {
            float4 v = r[k4];
            v.x *= sc; v.y *= sc; v.z *= sc; v.w *= sc;
            oo[k4 * 4 + 0] = v.x;
            oo[k4 * 4 + 1] = v.y;
            oo[k4 * 4 + 2] = v.z;
            oo[k4 * 4 + 3] = v.w;
            const float* w0 = &sW[(k4 * 4 + 0) * CD];
            const float* w1 = &sW[(k4 * 4 + 1) * CD];
            const float* w2 = &sW[(k4 * 4 + 2) * CD];
            const float* w3 = &sW[(k4 * 4 + 3) * CD];
#pragma unroll
            for (int c = 0; c < CD; c++)
                z[c] += v.x * w0[c] + v.y * w1[c] + v.z * w2[c] + v.w * w3[c];
        }
        float m = z[0];
#pragma unroll
        for (int c = 1; c < CD; c++) m = fmaxf(m, z[c]);
        float se = 0.f;
#pragma unroll
        for (int c = 0; c < CD; c++) se += expf(z[c] - m);
        float lse = m + logf(se);
        float* po = pred + (size_t)n * CD;
#pragma unroll
        for (int c = 0; c < CD; c++) po[c] = z[c] - lse;
    }

    __threadfence();
    __syncthreads();
    if (threadIdx.x == 0) {
        unsigned tk = atomicInc(&g_ctr, NPB - 1);
        s_last = (tk == NPB - 1);
    }
    __syncthreads();
    if (s_last) {
        __shared__ float sred[256];
        float s = 0.f;
        for (int i = threadIdx.x; i < NTR; i += 256) {
            int idx = tidx[i];
            s += pred[(size_t)idx * CD + labels[idx]];
        }
        sred[threadIdx.x] = s;
        __syncthreads();
        for (int o = 128; o > 0; o >>= 1) {
            if (threadIdx.x < o) sred[threadIdx.x] += sred[threadIdx.x + o];
            __syncthreads();
        }
        if (threadIdx.x == 0) out[0] = -sred[0] / (float)NTR;
    }
}

// ---------------------------------------------------------------------------
extern "C" void kernel_launch(void* const* d_in, const int* in_sizes, int n_in,
                              void* d_out, int out_size) {
    const float* feats  = (const float*)d_in[0];
    const float* W1     = (const float*)d_in[1];
    const float* b1     = (const float*)d_in[2];
    const float* W2     = (const float*)d_in[3];
    const float* b2     = (const float*)d_in[4];
    const float* W3     = (const float*)d_in[5];
    const float* b3     = (const float*)d_in[6];
    const int*   edges  = (const int*)d_in[7];
    const int*   labels = (const int*)d_in[8];
    const int*   tidx   = (const int*)d_in[9];

    float* out      = (float*)d_out;
    float* out_pred = out + 1;
    float* out_h    = out + 1 + (size_t)NN * CD;

    __half* t_ptr; cudaGetSymbolAddress((void**)&t_ptr, g_t);
    float*  h_ptr; cudaGetSymbolAddress((void**)&h_ptr, g_h);

    const int* src = edges;        // edge_list[0]
    const int* dst = edges + EE;   // edge_list[1]

    static cudaStream_t s2 = 0;
    static cudaEvent_t evFork = 0, evJoin = 0;
    if (s2 == 0) {
        cudaStreamCreate(&s2);
        cudaEventCreateWithFlags(&evFork, cudaEventDisableTiming);
        cudaEventCreateWithFlags(&evJoin, cudaEventDisableTiming);
    }

    const int gemm_blocks = (NN + 127) / 128;
    const int gath_blocks = (NN + 15) / 16;

    // #1: layer-0 GEMM on side stream (overlaps CSR build)
    cudaEventRecord(evFork, 0);
    cudaStreamWaitEvent(s2, evFork, 0);
    k_gemm<IND><<<gemm_blocks, 256, 0, s2>>>(feats, W1, t_ptr);
    cudaEventRecord(evJoin, s2);

    // ---- CSR build: #2 deg, #3 scanA(+B), #4 scanC, #5 fill
    k_deg<<<(EE + 255) / 256, 256>>>(dst);
    k_scanA<<<SCB, 256>>>();
    k_scanC<<<SCB, 256>>>();
    k_fill<<<(EE + 255) / 256, 256>>>(src, dst);

    cudaStreamWaitEvent(0, evJoin, 0);

    // #6: layer-0 gather (ncu -s 5 -c 1 capture target)
    k_gather<<<gath_blocks, 256>>>(t_ptr, h_ptr, b1, 0);

    // Hidden layers (relu)
    for (int l = 0; l < 2; l++) {
        k_gemm<HD><<<gemm_blocks, 256>>>(h_ptr, W2 + (size_t)l * HD * HD, t_ptr);
        k_gather<<<gath_blocks, 256>>>(t_ptr, h_ptr, b2 + (size_t)l * HD, 1);
    }

    // normalize + out_h + logits + log_softmax + fused loss
    k_normpred<<<NPB, 256>>>(h_ptr, out_h, W3, b3, out_pred, labels, tidx, out);
}

// round 14
// speedup vs baseline: 1.2268x; 1.0500x over previous
#include <cuda_runtime.h>
#include <cuda_fp16.h>
#include <math.h>

#define NN   50000
#define EE   1600000
#define IND  256
#define HD   64
#define CD   16
#define NTR  5000
#define NH   (NN*HD)
#define SCB  ((NN + 255) / 256)   // 196 scan blocks
#define NPB  ((NN + 255) / 256)   // normpred blocks

// Scratch (no allocs allowed)
__device__ __align__(16) __half   g_t[NH];     // x @ W  (fp16 message buffer)
__device__ __align__(16) float    g_h[NH];     // layer output (fp32)
__device__ __align__(16) unsigned g_e[EE];     // {u16 src | fp16 norm}, bucketed by dst
__device__ float g_dinv[NN];
__device__ int   g_deg[NN];                    // zero-init; self-restored by k_scan
__device__ int   g_off[NN];                    // bucket begin
__device__ int   g_end[NN];                    // bucket end
__device__ int   g_cur[NN];                    // fill cursors
__device__ unsigned g_pos;                     // zero-init; self-restored by k_scan
__device__ unsigned g_ctr;                     // zero-init; wraps (normpred)
__device__ unsigned g_ctr2;                    // zero-init; wraps (scan)

// ---------------------------------------------------------------------------
__device__ __forceinline__ unsigned long long fma2(unsigned long long a,
                                                   unsigned long long b,
                                                   unsigned long long c) {
    unsigned long long d;
    asm("fma.rn.f32x2 %0, %1, %2, %3;" : "=l"(d) : "l"(a), "l"(b), "l"(c));
    return d;
}
union U64F2 { unsigned long long u; float2 f; };
__device__ __forceinline__ float2 asf2(unsigned long long u) {
    U64F2 t; t.u = u; return t.f;
}
// unpack a uint4 of 8 halves into 8 floats
__device__ __forceinline__ void cvt8(uint4 r, float* f) {
    float2 p;
    p = __half22float2(*(__half2*)&r.x); f[0] = p.x; f[1] = p.y;
    p = __half22float2(*(__half2*)&r.y); f[2] = p.x; f[3] = p.y;
    p = __half22float2(*(__half2*)&r.z); f[4] = p.x; f[5] = p.y;
    p = __half22float2(*(__half2*)&r.w); f[6] = p.x; f[7] = p.y;
}
__device__ __forceinline__ float enorm(unsigned e) {
    return __half2float(__ushort_as_half((unsigned short)(e >> 16)));
}

// ---------------------------------------------------------------------------
__global__ void k_deg(const int* __restrict__ dst) {
    int e = blockIdx.x * blockDim.x + threadIdx.x;
    if (e < EE) atomicAdd(&g_deg[dst[e]], 1);
}

// Single-kernel CSR offsets: block scan + atomic base. Bucket order arbitrary.
__global__ void k_scan() {
    __shared__ int ss[256];
    __shared__ int sbase;
    __shared__ int s_last;
    int t = threadIdx.x;
    int idx = blockIdx.x * 256 + t;
    int d = 0;
    if (idx < NN) {
        d = g_deg[idx];
        g_deg[idx] = 0;                        // restore for next call
        g_dinv[idx] = rsqrtf((float)d + 1.0f); // +1 self-loop
    }
    ss[t] = d;
    __syncthreads();
#pragma unroll
    for (int o = 1; o < 256; o <<= 1) {
        int v = (t >= o) ? ss[t - o] : 0;
        __syncthreads();
        ss[t] += v;
        __syncthreads();
    }
    int inc = ss[t];
    if (t == 255) sbase = (int)atomicAdd(&g_pos, (unsigned)inc);
    __syncthreads();
    if (idx < NN) {
        int beg = sbase + inc - d;
        g_off[idx] = beg;
        g_cur[idx] = beg;
        g_end[idx] = beg + d;
    }
    // last-finishing block restores the cursor
    __threadfence();
    __syncthreads();
    if (t == 0) {
        unsigned tk = atomicInc(&g_ctr2, SCB - 1);
        s_last = (tk == SCB - 1);
    }
    __syncthreads();
    if (s_last && t == 0) g_pos = 0;
}

// Bucket edges by dst; one 4B packed store per edge.
__global__ void k_fill(const int* __restrict__ src, const int* __restrict__ dst) {
    int e = blockIdx.x * blockDim.x + threadIdx.x;
    if (e >= EE) return;
    int s = src[e], d = dst[e];
    int pos = atomicAdd(&g_cur[d], 1);
    float nm = g_dinv[s] * g_dinv[d];
    g_e[pos] = (unsigned)s |
               ((unsigned)__half_as_ushort(__float2half_rn(nm)) << 16);
}

// ---------------------------------------------------------------------------
// O[N,64] = A[N,K] @ W[K,64], fp32 compute, fp16 output.
template <int K>
__global__ void __launch_bounds__(256) k_gemm(const float* __restrict__ A,
                                              const float* __restrict__ W,
                                              __half* __restrict__ O) {
    __shared__ __align__(16) float sAT[32][132];
    __shared__ __align__(16) float sWd[32][136];
    const int tid = threadIdx.x;
    const int rg = tid & 15;
    const int cg = tid >> 4;
    const int rb = blockIdx.x * 128;

    unsigned long long acc[4][4];
#pragma unroll
    for (int i = 0; i < 4; i++)
#pragma unroll
        for (int j = 0; j < 4; j++) acc[i][j] = 0ull;

    for (int kc = 0; kc < K; kc += 32) {
#pragma unroll
        for (int it = 0; it < 4; it++) {
            int i = tid + it * 256;
            int r = i >> 3, k4 = i & 7;
            int row = rb + r;
            float4 v = (row < NN)
                ? *(const float4*)(A + (size_t)row * K + kc + k4 * 4)
                : make_float4(0.f, 0.f, 0.f, 0.f);
            sAT[k4 * 4 + 0][r] = v.x;
            sAT[k4 * 4 + 1][r] = v.y;
            sAT[k4 * 4 + 2][r] = v.z;
            sAT[k4 * 4 + 3][r] = v.w;
        }
#pragma unroll
        for (int it = 0; it < 2; it++) {
            int i = tid + it * 256;
            int c4 = i & 15, k = i >> 4;
            float4 v = *(const float4*)(W + (size_t)(kc + k) * HD + c4 * 4);
            float2* wp = (float2*)&sWd[k][c4 * 8];
            wp[0] = make_float2(v.x, v.x);
            wp[1] = make_float2(v.y, v.y);
            wp[2] = make_float2(v.z, v.z);
            wp[3] = make_float2(v.w, v.w);
        }
        __syncthreads();
#pragma unroll 8
        for (int k = 0; k < 32; k++) {
            ulonglong2 a01 = *(const ulonglong2*)&sAT[k][rg * 8];
            ulonglong2 a23 = *(const ulonglong2*)&sAT[k][rg * 8 + 4];
            ulonglong2 w01 = *(const ulonglong2*)&sWd[k][cg * 8];
            ulonglong2 w23 = *(const ulonglong2*)&sWd[k][cg * 8 + 4];
            acc[0][0] = fma2(a01.x, w01.x, acc[0][0]);
            acc[0][1] = fma2(a01.x, w01.y, acc[0][1]);
            acc[0][2] = fma2(a01.x, w23.x, acc[0][2]);
            acc[0][3] = fma2(a01.x, w23.y, acc[0][3]);
            acc[1][0] = fma2(a01.y, w01.x, acc[1][0]);
            acc[1][1] = fma2(a01.y, w01.y, acc[1][1]);
            acc[1][2] = fma2(a01.y, w23.x, acc[1][2]);
            acc[1][3] = fma2(a01.y, w23.y, acc[1][3]);
            acc[2][0] = fma2(a23.x, w01.x, acc[2][0]);
            acc[2][1] = fma2(a23.x, w01.y, acc[2][1]);
            acc[2][2] = fma2(a23.x, w23.x, acc[2][2]);
            acc[2][3] = fma2(a23.x, w23.y, acc[2][3]);
            acc[3][0] = fma2(a23.y, w01.x, acc[3][0]);
            acc[3][1] = fma2(a23.y, w01.y, acc[3][1]);
            acc[3][2] = fma2(a23.y, w23.x, acc[3][2]);
            acc[3][3] = fma2(a23.y, w23.y, acc[3][3]);
        }
        __syncthreads();
    }
#pragma unroll
    for (int rp = 0; rp < 4; rp++) {
        float2 c0 = asf2(acc[rp][0]);
        float2 c1 = asf2(acc[rp][1]);
        float2 c2 = asf2(acc[rp][2]);
        float2 c3 = asf2(acc[rp][3]);
        int row0 = rb + rg * 8 + rp * 2;
        if (row0 < NN) {
            union { uint2 u; __half2 h[2]; } pk;
            pk.h[0] = __floats2half2_rn(c0.x, c1.x);
            pk.h[1] = __floats2half2_rn(c2.x, c3.x);
            *(uint2*)(O + (size_t)row0 * HD + cg * 4) = pk.u;
        }
        if (row0 + 1 < NN) {
            union { uint2 u; __half2 h[2]; } pk;
            pk.h[0] = __floats2half2_rn(c0.y, c1.y);
            pk.h[1] = __floats2half2_rn(c2.y, c3.y);
            *(uint2*)(O + (size_t)(row0 + 1) * HD + cg * 4) = pk.u;
        }
    }
}

// ---------------------------------------------------------------------------
// CSR gather: 8 lanes/node (lane q owns features 8q..8q+7, one uint4/row),
// 4 edges per uint4 edge-load, fp32 accumulate, self-loop+bias+relu fused.
__global__ void __launch_bounds__(256) k_gather(const __half* __restrict__ t,
                                                float* __restrict__ h,
                                                const float* __restrict__ b,
                                                int relu) {
    int node = blockIdx.x * 32 + (threadIdx.x >> 3);
    int q = threadIdx.x & 7;
    if (node >= NN) return;
    const uint4* tv = (const uint4*)t;   // 8 uint4 per 64-half row

    float di = g_dinv[node];
    float di2 = di * di;
    float a0[8], a1[8], f[8];
    cvt8(__ldg(&tv[(size_t)node * 8 + q]), f);
#pragma unroll
    for (int j = 0; j < 8; j++) { a0[j] = f[j] * di2; a1[j] = 0.f; }

    int i = g_off[node], end = g_end[node];
    // prologue: align i to 4 for uint4 edge loads
    while ((i & 3) && i < end) {
        unsigned e = __ldg(&g_e[i]);
        cvt8(__ldg(&tv[(size_t)(e & 0xFFFFu) * 8 + q]), f);
        float nm = enorm(e);
#pragma unroll
        for (int j = 0; j < 8; j++) a0[j] += nm * f[j];
        i++;
    }
    for (; i + 4 <= end; i += 4) {
        uint4 e4 = __ldg((const uint4*)&g_e[i]);
        uint4 r0 = __ldg(&tv[(size_t)(e4.x & 0xFFFFu) * 8 + q]);
        uint4 r1 = __ldg(&tv[(size_t)(e4.y & 0xFFFFu) * 8 + q]);
        uint4 r2 = __ldg(&tv[(size_t)(e4.z & 0xFFFFu) * 8 + q]);
        uint4 r3 = __ldg(&tv[(size_t)(e4.w & 0xFFFFu) * 8 + q]);
        float n0 = enorm(e4.x), n1 = enorm(e4.y), n2 = enorm(e4.z), n3 = enorm(e4.w);
        cvt8(r0, f);
#pragma unroll
        for (int j = 0; j < 8; j++) a0[j] += n0 * f[j];
        cvt8(r1, f);
#pragma unroll
        for (int j = 0; j < 8; j++) a1[j] += n1 * f[j];
        cvt8(r2, f);
#pragma unroll
        for (int j = 0; j < 8; j++) a0[j] += n2 * f[j];
        cvt8(r3, f);
#pragma unroll
        for (int j = 0; j < 8; j++) a1[j] += n3 * f[j];
    }
    for (; i < end; i++) {
        unsigned e = __ldg(&g_e[i]);
        cvt8(__ldg(&tv[(size_t)(e & 0xFFFFu) * 8 + q]), f);
        float nm = enorm(e);
#pragma unroll
        for (int j = 0; j < 8; j++) a0[j] += nm * f[j];
    }

    const float4* bv = (const float4*)(b + q * 8);
    float4 b0 = __ldg(bv), b1 = __ldg(bv + 1);
    float r0x = a0[0] + a1[0] + b0.x, r0y = a0[1] + a1[1] + b0.y;
    float r0z = a0[2] + a1[2] + b0.z, r0w = a0[3] + a1[3] + b0.w;
    float r1x = a0[4] + a1[4] + b1.x, r1y = a0[5] + a1[5] + b1.y;
    float r1z = a0[6] + a1[6] + b1.z, r1w = a0[7] + a1[7] + b1.w;
    if (relu) {
        r0x = fmaxf(r0x, 0.f); r0y = fmaxf(r0y, 0.f);
        r0z = fmaxf(r0z, 0.f); r0w = fmaxf(r0w, 0.f);
        r1x = fmaxf(r1x, 0.f); r1y = fmaxf(r1y, 0.f);
        r1z = fmaxf(r1z, 0.f); r1w = fmaxf(r1w, 0.f);
    }
    float4* hv = (float4*)(h + (size_t)node * HD + q * 8);
    hv[0] = make_float4(r0x, r0y, r0z, r0w);
    hv[1] = make_float4(r1x, r1y, r1z, r1w);
}

// ---------------------------------------------------------------------------
// Fused: L2-normalize -> out_h, logits -> log_softmax -> out_pred, last-block NLL.
__global__ void k_normpred(const float* __restrict__ h, float* __restrict__ out_h,
                           const float* __restrict__ W3, const float* __restrict__ b3,
                           float* __restrict__ pred,
                           const int* __restrict__ labels, const int* __restrict__ tidx,
                           float* __restrict__ out) {
    __shared__ float sW[HD * CD];
    __shared__ float sb[CD];
    __shared__ int s_last;
    for (int i = threadIdx.x; i < HD * CD; i += blockDim.x) sW[i] = W3[i];
    if (threadIdx.x < CD) sb[threadIdx.x] = b3[threadIdx.x];
    __syncthreads();
    int n = blockIdx.x * blockDim.x + threadIdx.x;

    if (n < NN) {
        const float4* hv = (const float4*)(h + (size_t)n * HD);
        float4 r[16];
        float ss = 0.f;
#pragma unroll
        for (int i = 0; i < 16; i++) {
            float4 v = hv[i];
            r[i] = v;
            ss += v.x * v.x + v.y * v.y + v.z * v.z + v.w * v.w;
        }
        float sc = 1.0f / fmaxf(sqrtf(ss), 1e-12f);

        float z[CD];
#pragma unroll
        for (int c = 0; c < CD; c++) z[c] = sb[c];
        float* oo = out_h + (size_t)n * HD;
#pragma unroll
        for (int k4 = 0; k4 < 16; k4++) {
            float4 v = r[k4];
            v.x *= sc; v.y *= sc; v.z *= sc; v.w *= sc;
            oo[k4 * 4 + 0] = v.x;
            oo[k4 * 4 + 1] = v.y;
            oo[k4 * 4 + 2] = v.z;
            oo[k4 * 4 + 3] = v.w;
            const float* w0 = &sW[(k4 * 4 + 0) * CD];
            const float* w1 = &sW[(k4 * 4 + 1) * CD];
            const float* w2 = &sW[(k4 * 4 + 2) * CD];
            const float* w3 = &sW[(k4 * 4 + 3) * CD];
#pragma unroll
            for (int c = 0; c < CD; c++)
                z[c] += v.x * w0[c] + v.y * w1[c] + v.z * w2[c] + v.w * w3[c];
        }
        float m = z[0];
#pragma unroll
        for (int c = 1; c < CD; c++) m = fmaxf(m, z[c]);
        float se = 0.f;
#pragma unroll
        for (int c = 0; c < CD; c++) se += expf(z[c] - m);
        float lse = m + logf(se);
        float* po = pred + (size_t)n * CD;
#pragma unroll
        for (int c = 0; c < CD; c++) po[c] = z[c] - lse;
    }

    __threadfence();
    __syncthreads();
    if (threadIdx.x == 0) {
        unsigned tk = atomicInc(&g_ctr, NPB - 1);
        s_last = (tk == NPB - 1);
    }
    __syncthreads();
    if (s_last) {
        __shared__ float sred[256];
        float s = 0.f;
        for (int i = threadIdx.x; i < NTR; i += 256) {
            int idx = tidx[i];
            s += pred[(size_t)idx * CD + labels[idx]];
        }
        sred[threadIdx.x] = s;
        __syncthreads();
        for (int o = 128; o > 0; o >>= 1) {
            if (threadIdx.x < o) sred[threadIdx.x] += sred[threadIdx.x + o];
            __syncthreads();
        }
        if (threadIdx.x == 0) out[0] = -sred[0] / (float)NTR;
    }
}

// ---------------------------------------------------------------------------
extern "C" void kernel_launch(void* const* d_in, const int* in_sizes, int n_in,
                              void* d_out, int out_size) {
    const float* feats  = (const float*)d_in[0];
    const float* W1     = (const float*)d_in[1];
    const float* b1     = (const float*)d_in[2];
    const float* W2     = (const float*)d_in[3];
    const float* b2     = (const float*)d_in[4];
    const float* W3     = (const float*)d_in[5];
    const float* b3     = (const float*)d_in[6];
    const int*   edges  = (const int*)d_in[7];
    const int*   labels = (const int*)d_in[8];
    const int*   tidx   = (const int*)d_in[9];

    float* out      = (float*)d_out;
    float* out_pred = out + 1;
    float* out_h    = out + 1 + (size_t)NN * CD;

    __half* t_ptr; cudaGetSymbolAddress((void**)&t_ptr, g_t);
    float*  h_ptr; cudaGetSymbolAddress((void**)&h_ptr, g_h);

    const int* src = edges;        // edge_list[0]
    const int* dst = edges + EE;   // edge_list[1]

    static cudaStream_t s2 = 0;
    static cudaEvent_t evFork = 0, evJoin = 0;
    if (s2 == 0) {
        cudaStreamCreate(&s2);
        cudaEventCreateWithFlags(&evFork, cudaEventDisableTiming);
        cudaEventCreateWithFlags(&evJoin, cudaEventDisableTiming);
    }

    const int gemm_blocks = (NN + 127) / 128;
    const int gath_blocks = (NN + 31) / 32;

    // #1: layer-0 GEMM on side stream (overlaps CSR build)
    cudaEventRecord(evFork, 0);
    cudaStreamWaitEvent(s2, evFork, 0);
    k_gemm<IND><<<gemm_blocks, 256, 0, s2>>>(feats, W1, t_ptr);
    cudaEventRecord(evJoin, s2);

    // ---- CSR build: #2 deg, #3 scan, #4 fill
    k_deg<<<(EE + 255) / 256, 256>>>(dst);
    k_scan<<<SCB, 256>>>();
    k_fill<<<(EE + 255) / 256, 256>>>(src, dst);

    cudaStreamWaitEvent(0, evJoin, 0);

    // #5: layer-0 gather
    k_gather<<<gath_blocks, 256>>>(t_ptr, h_ptr, b1, 0);

    // Hidden layers (relu)
    for (int l = 0; l < 2; l++) {
        k_gemm<HD><<<gemm_blocks, 256>>>(h_ptr, W2 + (size_t)l * HD * HD, t_ptr);
        k_gather<<<gath_blocks, 256>>>(t_ptr, h_ptr, b2 + (size_t)l * HD, 1);
    }

    // normalize + out_h + logits + log_softmax + fused loss
    k_normpred<<<NPB, 256>>>(h_ptr, out_h, W3, b3, out_pred, labels, tidx, out);
}